// round 1
// baseline (speedup 1.0000x reference)
#include <cuda_runtime.h>

// ---------------------------------------------------------------------------
// MultiHeadedAttention: B=4, S=2048, D_MODEL=1024, H=16, DK=DV=64
// Round 1: correct fp32 baseline.
//   k1: SGEMM projections  Q/K/V = X @ W   -> [B,H,S,64] layout
//   k2: flash attention (64-row Q tiles, online softmax, mask in SMEM)
//   k3: SGEMM output projection  Y = attn @ w_out
//   k4: residual + LayerNorm fused
// ---------------------------------------------------------------------------

#define NEGV (-1e9f)
#define MINIT (-1e38f)

// scratch (device globals -- no allocation allowed)
__device__ float g_q[4 * 16 * 2048 * 64];
__device__ float g_k[4 * 16 * 2048 * 64];
__device__ float g_v[4 * 16 * 2048 * 64];
__device__ float g_attn[8192 * 1024];
__device__ float g_y[8192 * 1024];

// ---------------------------------------------------------------------------
// Tiled fp32 SGEMM: C[M,N] = A[M,K] @ B[K,N]; 64x64 tile, kt=16, 256 threads.
// mode 0: plain row-major out.  mode 1: write to [B,H,S,64] head layout.
// ---------------------------------------------------------------------------
__global__ void __launch_bounds__(256) sgemm_kernel(
    const float* __restrict__ A, const float* __restrict__ B,
    float* __restrict__ C, int M, int N, int K, int mode)
{
    __shared__ float As[16][68];   // transposed: As[k][m_local]
    __shared__ float Bs[16][68];

    int tid = threadIdx.x;
    int tx = tid & 15, ty = tid >> 4;
    int m0 = blockIdx.y * 64, n0 = blockIdx.x * 64;

    int arow = tid >> 2, acol = (tid & 3) << 2;   // A tile load: 64 rows x 16 k
    int brow = tid >> 4, bcol = (tid & 15) << 2;  // B tile load: 16 rows x 64 n

    const float* Ap = A + (size_t)(m0 + arow) * K + acol;
    const float* Bp = B + (size_t)brow * N + n0 + bcol;

    float acc[4][4];
#pragma unroll
    for (int i = 0; i < 4; i++)
#pragma unroll
        for (int j = 0; j < 4; j++) acc[i][j] = 0.f;

    for (int k0 = 0; k0 < K; k0 += 16) {
        float4 a4 = *(const float4*)Ap;
        float4 b4 = *(const float4*)Bp;
        Ap += 16;
        Bp += (size_t)16 * N;
        __syncthreads();
        As[acol + 0][arow] = a4.x;
        As[acol + 1][arow] = a4.y;
        As[acol + 2][arow] = a4.z;
        As[acol + 3][arow] = a4.w;
        *(float4*)&Bs[brow][bcol] = b4;
        __syncthreads();
#pragma unroll
        for (int kk = 0; kk < 16; kk++) {
            float4 av = *(const float4*)&As[kk][ty << 2];
            float4 bv = *(const float4*)&Bs[kk][tx << 2];
            float ar[4] = {av.x, av.y, av.z, av.w};
            float br[4] = {bv.x, bv.y, bv.z, bv.w};
#pragma unroll
            for (int i = 0; i < 4; i++)
#pragma unroll
                for (int j = 0; j < 4; j++)
                    acc[i][j] += ar[i] * br[j];
        }
    }

#pragma unroll
    for (int i = 0; i < 4; i++) {
        int m = m0 + (ty << 2) + i;
        int n = n0 + (tx << 2);
        float4 r = make_float4(acc[i][0], acc[i][1], acc[i][2], acc[i][3]);
        if (mode == 0) {
            *(float4*)&C[(size_t)m * N + n] = r;
        } else {
            int b = m >> 11, s = m & 2047;     // S = 2048
            int h = n >> 6, d = n & 63;        // 64 per head
            size_t idx = (((size_t)(b * 16 + h) * 2048 + s) << 6) + d;
            *(float4*)&C[idx] = r;
        }
    }
}

// ---------------------------------------------------------------------------
// Flash attention. grid = (S/64, H, B), 256 threads.
// Q/K/V in [B,H,S,64]; out written to [B,S,H*64] for the output projection.
// Dynamic SMEM layout (floats): Qs 4096 | Ks 4096 (swizzled) | Vs 4096 |
//   Ss 64*65 | rowm 64 | rowl 64 | rowa 64 | Ms(int) 64*65
// ---------------------------------------------------------------------------
#define ATTN_SMEM ((4096 * 3 + 64 * 65 + 192 + 64 * 65) * 4)

__global__ void __launch_bounds__(256) attn_kernel(
    const float* __restrict__ Q, const float* __restrict__ Kg,
    const float* __restrict__ Vg, const int* __restrict__ mask,
    float* __restrict__ O)
{
    extern __shared__ float sm[];
    float* Qs   = sm;                 // [64][64]
    float* Ks   = Qs + 4096;          // [64][64], 16B-chunk swizzled
    float* Vs   = Ks + 4096;          // [64][64]
    float* Ss   = Vs + 4096;          // [64][65]
    float* rowm = Ss + 64 * 65;
    float* rowl = rowm + 64;
    float* rowa = rowl + 64;
    int*   Ms   = (int*)(rowa + 64);  // [64][65]

    int tid = threadIdx.x;
    int qt = blockIdx.x, h = blockIdx.y, b = blockIdx.z;
    int qbase = qt * 64;

    const float* qp  = Q  + (((size_t)(b * 16 + h) * 2048 + qbase) << 6);
    const float* kp0 = Kg + (((size_t)(b * 16 + h) * 2048) << 6);
    const float* vp0 = Vg + (((size_t)(b * 16 + h) * 2048) << 6);
    const int*   mp  = mask + ((size_t)b * 2048 + qbase) * 2048;

    // load Q tile
#pragma unroll
    for (int i = 0; i < 4; i++) {
        int lin = tid + i * 256;
        int row = lin >> 4, c = lin & 15;
        *(float4*)&Qs[row * 64 + (c << 2)] =
            *(const float4*)&qp[row * 64 + (c << 2)];
    }
    if (tid < 64) { rowm[tid] = MINIT; rowl[tid] = 0.f; }

    int r0 = (tid >> 4) << 2;      // output row group (4 rows)
    int c0 = (tid & 15) << 2;      // key-col / dv-col group (4 cols)
    int ksel = tid & 15;           // swizzle selector = j>>2 for this thread

    float Oa[4][4];
#pragma unroll
    for (int i = 0; i < 4; i++)
#pragma unroll
        for (int j = 0; j < 4; j++) Oa[i][j] = 0.f;

    for (int kb = 0; kb < 2048; kb += 64) {
        __syncthreads();
        const float* kp = kp0 + ((size_t)kb << 6);
        const float* vp = vp0 + ((size_t)kb << 6);
#pragma unroll
        for (int i = 0; i < 4; i++) {
            int lin = tid + i * 256;
            int row = lin >> 4, c = lin & 15;
            float4 kv = *(const float4*)&kp[row * 64 + (c << 2)];
            int sw = c ^ ((row >> 2) & 15);
            *(float4*)&Ks[row * 64 + (sw << 2)] = kv;
            *(float4*)&Vs[row * 64 + (c << 2)] =
                *(const float4*)&vp[row * 64 + (c << 2)];
            int4 mv = *(const int4*)&mp[(size_t)row * 2048 + kb + (c << 2)];
            int mb = row * 65 + (c << 2);
            Ms[mb] = mv.x; Ms[mb + 1] = mv.y; Ms[mb + 2] = mv.z; Ms[mb + 3] = mv.w;
        }
        __syncthreads();

        // ---- scores: S = Q K^T * 0.125 ----
        float acc[4][4];
#pragma unroll
        for (int i = 0; i < 4; i++)
#pragma unroll
            for (int j = 0; j < 4; j++) acc[i][j] = 0.f;

#pragma unroll
        for (int dc = 0; dc < 16; dc++) {
            float4 qa[4], kv[4];
#pragma unroll
            for (int i = 0; i < 4; i++)
                qa[i] = *(const float4*)&Qs[(r0 + i) * 64 + (dc << 2)];
#pragma unroll
            for (int j = 0; j < 4; j++)
                kv[j] = *(const float4*)&Ks[(c0 + j) * 64 + ((dc ^ ksel) << 2)];
#pragma unroll
            for (int i = 0; i < 4; i++)
#pragma unroll
                for (int j = 0; j < 4; j++) {
                    acc[i][j] += qa[i].x * kv[j].x;
                    acc[i][j] += qa[i].y * kv[j].y;
                    acc[i][j] += qa[i].z * kv[j].z;
                    acc[i][j] += qa[i].w * kv[j].w;
                }
        }
#pragma unroll
        for (int i = 0; i < 4; i++)
#pragma unroll
            for (int j = 0; j < 4; j++)
                Ss[(r0 + i) * 65 + c0 + j] = acc[i][j] * 0.125f;
        __syncthreads();

        // ---- online softmax (one thread per row) ----
        if (tid < 64) {
            int i = tid;
            float mo = rowm[i];
            float mx = mo;
#pragma unroll 8
            for (int j = 0; j < 64; j++) {
                float s = Ms[i * 65 + j] ? Ss[i * 65 + j] : NEGV;
                Ss[i * 65 + j] = s;
                mx = fmaxf(mx, s);
            }
            float alpha = __expf(mo - mx);
            float sum = 0.f;
#pragma unroll 8
            for (int j = 0; j < 64; j++) {
                float p = __expf(Ss[i * 65 + j] - mx);
                Ss[i * 65 + j] = p;
                sum += p;
            }
            rowm[i] = mx;
            rowl[i] = rowl[i] * alpha + sum;
            rowa[i] = alpha;
        }
        __syncthreads();

        // ---- O = O*alpha + P V ----
        float al[4];
#pragma unroll
        for (int i = 0; i < 4; i++) al[i] = rowa[r0 + i];
#pragma unroll
        for (int i = 0; i < 4; i++)
#pragma unroll
            for (int j = 0; j < 4; j++) Oa[i][j] *= al[i];

#pragma unroll 4
        for (int j = 0; j < 64; j++) {
            float4 vv = *(const float4*)&Vs[j * 64 + c0];
            float pr[4];
#pragma unroll
            for (int i = 0; i < 4; i++) pr[i] = Ss[(r0 + i) * 65 + j];
#pragma unroll
            for (int i = 0; i < 4; i++) {
                Oa[i][0] += pr[i] * vv.x;
                Oa[i][1] += pr[i] * vv.y;
                Oa[i][2] += pr[i] * vv.z;
                Oa[i][3] += pr[i] * vv.w;
            }
        }
    }

    // final normalize and write to [B,S,H*64]
#pragma unroll
    for (int i = 0; i < 4; i++) {
        float linv = 1.f / rowl[r0 + i];
        size_t idx = ((size_t)(b * 2048 + qbase + r0 + i)) * 1024 + h * 64 + c0;
        float4 r = make_float4(Oa[i][0] * linv, Oa[i][1] * linv,
                               Oa[i][2] * linv, Oa[i][3] * linv);
        *(float4*)&O[idx] = r;
    }
}

// ---------------------------------------------------------------------------
// residual + LayerNorm: out = LN(Y + R) * g + b ; one block per row of 1024
// ---------------------------------------------------------------------------
__global__ void __launch_bounds__(256) ln_kernel(
    const float* __restrict__ Y, const float* __restrict__ R,
    const float* __restrict__ g, const float* __restrict__ bt,
    float* __restrict__ out)
{
    __shared__ float red[2][8];
    int row = blockIdx.x;
    int tid = threadIdx.x;
    int lane = tid & 31, wid = tid >> 5;

    const float4* yp = (const float4*)(Y + (size_t)row * 1024);
    const float4* rp = (const float4*)(R + (size_t)row * 1024);
    float4 y4 = yp[tid];
    float4 r4 = rp[tid];
    float x0 = y4.x + r4.x, x1 = y4.y + r4.y, x2 = y4.z + r4.z, x3 = y4.w + r4.w;

    float sum = x0 + x1 + x2 + x3;
    float sq  = x0 * x0 + x1 * x1 + x2 * x2 + x3 * x3;
#pragma unroll
    for (int off = 16; off > 0; off >>= 1) {
        sum += __shfl_xor_sync(0xffffffff, sum, off);
        sq  += __shfl_xor_sync(0xffffffff, sq,  off);
    }
    if (lane == 0) { red[0][wid] = sum; red[1][wid] = sq; }
    __syncthreads();
    if (tid == 0) {
        float ts = 0.f, tq = 0.f;
#pragma unroll
        for (int w = 0; w < 8; w++) { ts += red[0][w]; tq += red[1][w]; }
        red[0][0] = ts; red[1][0] = tq;
    }
    __syncthreads();
    float mu  = red[0][0] * (1.f / 1024.f);
    float var = red[1][0] * (1.f / 1024.f) - mu * mu;
    float rstd = rsqrtf(var + 1e-6f);

    float4 g4 = ((const float4*)g)[tid];
    float4 b4 = ((const float4*)bt)[tid];
    float4 o;
    o.x = (x0 - mu) * rstd * g4.x + b4.x;
    o.y = (x1 - mu) * rstd * g4.y + b4.y;
    o.z = (x2 - mu) * rstd * g4.z + b4.z;
    o.w = (x3 - mu) * rstd * g4.w + b4.w;
    ((float4*)(out + (size_t)row * 1024))[tid] = o;
}

// ---------------------------------------------------------------------------
extern "C" void kernel_launch(void* const* d_in, const int* in_sizes, int n_in,
                              void* d_out, int out_size)
{
    const float* query = (const float*)d_in[0];
    const float* key   = (const float*)d_in[1];
    const float* value = (const float*)d_in[2];
    const int*   mask  = (const int*)d_in[3];
    const float* w_qs  = (const float*)d_in[4];
    const float* w_ks  = (const float*)d_in[5];
    const float* w_vs  = (const float*)d_in[6];
    const float* w_out = (const float*)d_in[7];
    const float* ln_g  = (const float*)d_in[8];
    const float* ln_b  = (const float*)d_in[9];
    float* out = (float*)d_out;

    float *q, *k, *v, *attn, *y;
    cudaGetSymbolAddress((void**)&q,    g_q);
    cudaGetSymbolAddress((void**)&k,    g_k);
    cudaGetSymbolAddress((void**)&v,    g_v);
    cudaGetSymbolAddress((void**)&attn, g_attn);
    cudaGetSymbolAddress((void**)&y,    g_y);

    dim3 gg(16, 128);   // N/64, M/64 for M=8192, N=1024

    sgemm_kernel<<<gg, 256>>>(query, w_qs, q, 8192, 1024, 1024, 1);
    sgemm_kernel<<<gg, 256>>>(key,   w_ks, k, 8192, 1024, 1024, 1);
    sgemm_kernel<<<gg, 256>>>(value, w_vs, v, 8192, 1024, 1024, 1);

    cudaFuncSetAttribute(attn_kernel,
                         cudaFuncAttributeMaxDynamicSharedMemorySize,
                         ATTN_SMEM);
    attn_kernel<<<dim3(32, 16, 4), 256, ATTN_SMEM>>>(q, k, v, mask, attn);

    sgemm_kernel<<<gg, 256>>>(attn, w_out, y, 8192, 1024, 1024, 0);

    ln_kernel<<<8192, 256>>>(y, query, ln_g, ln_b, out);
}

// round 2
// speedup vs baseline: 2.1952x; 2.1952x over previous
#include <cuda_runtime.h>

// ---------------------------------------------------------------------------
// MultiHeadedAttention: B=4, S=2048, D_MODEL=1024, H=16, DK=DV=64
// Round 2: tf32 tensor-core path (mma.sync.m16n8k8) for all GEMMs + attention.
// ---------------------------------------------------------------------------

#define NEGV (-1e9f)
#define MINIT (-1e38f)

// scratch (device globals -- no allocation allowed)
__device__ float g_q[4 * 16 * 2048 * 64];
__device__ float g_k[4 * 16 * 2048 * 64];
__device__ float g_v[4 * 16 * 2048 * 64];   // holds V^T per head: [B,H,64,2048]
__device__ float g_attn[8192 * 1024];
__device__ float g_y[8192 * 1024];

// ---- tf32 helpers ---------------------------------------------------------
__device__ __forceinline__ unsigned f2tf(float f) {
    unsigned u;
    asm("cvt.rna.tf32.f32 %0, %1;" : "=r"(u) : "f"(f));
    return u;
}

__device__ __forceinline__ void mma_tf32(float c[4], const unsigned a[4],
                                         const unsigned b[2]) {
    asm volatile(
        "mma.sync.aligned.m16n8k8.row.col.f32.tf32.tf32.f32 "
        "{%0,%1,%2,%3}, {%4,%5,%6,%7}, {%8,%9}, {%0,%1,%2,%3};"
        : "+f"(c[0]), "+f"(c[1]), "+f"(c[2]), "+f"(c[3])
        : "r"(a[0]), "r"(a[1]), "r"(a[2]), "r"(a[3]), "r"(b[0]), "r"(b[1]));
}

// ---------------------------------------------------------------------------
// tf32 GEMM: C[M,N] = A[M,K] @ B[K,N], fp32 in/out.
// Block tile 128x128, k-tile 32, 256 threads (8 warps as 2M x 4N, warp 64x32).
// mode 0: row-major out.  mode 1: [B,H,S,64].  mode 2: V^T [B,H,64,S].
// ---------------------------------------------------------------------------
__global__ void __launch_bounds__(256) gemm_tc(
    const float* __restrict__ A, const float* __restrict__ B,
    float* __restrict__ C, int M, int N, int K, int mode)
{
    __shared__ unsigned As[128 * 36];   // stride 36: frag LDS conflict-free
    __shared__ unsigned Bs[32 * 132];   // stride 132 (== 4 mod 32)

    int tid = threadIdx.x;
    int wid = tid >> 5, lane = tid & 31;
    int r = lane >> 2, c = lane & 3, g = lane >> 2;
    int m0 = blockIdx.y * 128, n0 = blockIdx.x * 128;
    int wm = (wid & 1) * 64, wn = (wid >> 1) * 32;

    float acc[4][4][4];
#pragma unroll
    for (int mt = 0; mt < 4; mt++)
#pragma unroll
        for (int nt = 0; nt < 4; nt++)
#pragma unroll
            for (int i = 0; i < 4; i++) acc[mt][nt][i] = 0.f;

    for (int k0 = 0; k0 < K; k0 += 32) {
        __syncthreads();
#pragma unroll
        for (int i = 0; i < 4; i++) {
            int lin = tid + i * 256;
            int row = lin >> 3, c4 = (lin & 7) << 2;     // A: 128 x 32
            float4 a4 = *(const float4*)&A[(size_t)(m0 + row) * K + k0 + c4];
            uint4 ua;
            ua.x = f2tf(a4.x); ua.y = f2tf(a4.y);
            ua.z = f2tf(a4.z); ua.w = f2tf(a4.w);
            *(uint4*)&As[row * 36 + c4] = ua;
            int rowb = lin >> 5, cb = (lin & 31) << 2;   // B: 32 x 128
            float4 b4 = *(const float4*)&B[(size_t)(k0 + rowb) * N + n0 + cb];
            uint4 ub;
            ub.x = f2tf(b4.x); ub.y = f2tf(b4.y);
            ub.z = f2tf(b4.z); ub.w = f2tf(b4.w);
            *(uint4*)&Bs[rowb * 132 + cb] = ub;
        }
        __syncthreads();

#pragma unroll
        for (int ks = 0; ks < 4; ks++) {
            int k8 = ks * 8;
            unsigned ua[4][4], ub[4][2];
#pragma unroll
            for (int mt = 0; mt < 4; mt++) {
                int rr = wm + mt * 16 + r;
                ua[mt][0] = As[rr * 36 + k8 + c];
                ua[mt][1] = As[(rr + 8) * 36 + k8 + c];
                ua[mt][2] = As[rr * 36 + k8 + c + 4];
                ua[mt][3] = As[(rr + 8) * 36 + k8 + c + 4];
            }
#pragma unroll
            for (int nt = 0; nt < 4; nt++) {
                int cn = wn + nt * 8 + g;
                ub[nt][0] = Bs[(k8 + c) * 132 + cn];
                ub[nt][1] = Bs[(k8 + c + 4) * 132 + cn];
            }
#pragma unroll
            for (int mt = 0; mt < 4; mt++)
#pragma unroll
                for (int nt = 0; nt < 4; nt++)
                    mma_tf32(acc[mt][nt], ua[mt], ub[nt]);
        }
    }

#pragma unroll
    for (int mt = 0; mt < 4; mt++) {
#pragma unroll
        for (int nt = 0; nt < 4; nt++) {
            int rr = m0 + wm + mt * 16 + r;
            int cc = n0 + wn + nt * 8 + 2 * c;
            float* a4 = acc[mt][nt];
            if (mode == 0) {
                *(float2*)&C[(size_t)rr * N + cc] = make_float2(a4[0], a4[1]);
                *(float2*)&C[(size_t)(rr + 8) * N + cc] = make_float2(a4[2], a4[3]);
            } else if (mode == 1) {
                int b = rr >> 11, s = rr & 2047;
                int h = cc >> 6, d = cc & 63;
                size_t idx = (((size_t)(b * 16 + h) * 2048 + s) << 6) + d;
                *(float2*)&C[idx] = make_float2(a4[0], a4[1]);
                int b2 = (rr + 8) >> 11, s2 = (rr + 8) & 2047;
                size_t idx2 = (((size_t)(b2 * 16 + h) * 2048 + s2) << 6) + d;
                *(float2*)&C[idx2] = make_float2(a4[2], a4[3]);
            } else {  // mode 2: V^T [B,H,64,2048]
                int b = rr >> 11, s = rr & 2047;
                int h = cc >> 6, d = cc & 63;
                size_t base = ((size_t)(b * 16 + h) * 64 + d) * 2048;
                C[base + s] = a4[0];
                C[base + 2048 + s] = a4[1];
                int b2 = (rr + 8) >> 11, s2 = (rr + 8) & 2047;
                size_t base2 = ((size_t)(b2 * 16 + h) * 64 + d) * 2048;
                C[base2 + s2] = a4[2];
                C[base2 + 2048 + s2] = a4[3];
            }
        }
    }
}

// ---------------------------------------------------------------------------
// Flash attention with tf32 mma. grid = (S/64, H, B), 256 threads (8 warps).
// Q,K in [B,H,S,64]; V^T in [B,H,64,S]; out -> [B,S,H*64].
// SMEM (all stride 68 == 4 mod 32 -> conflict-free frag loads):
//   Qs[64*68] Ks[64*68] Vs[64*68] Ss[64*68] + rowm/rowl/rowa[64]
// ---------------------------------------------------------------------------
#define ATTN_SMEM ((4 * 64 * 68 + 192) * 4)

__global__ void __launch_bounds__(256) attn_tc(
    const float* __restrict__ Q, const float* __restrict__ Kg,
    const float* __restrict__ Vt, const int* __restrict__ mask,
    float* __restrict__ O)
{
    extern __shared__ unsigned smu[];
    unsigned* Qs = smu;
    unsigned* Ks = Qs + 64 * 68;
    unsigned* Vs = Ks + 64 * 68;
    float*    Ssf = (float*)(Vs + 64 * 68);
    unsigned* Ssu = (unsigned*)Ssf;
    float* rowm = Ssf + 64 * 68;
    float* rowl = rowm + 64;
    float* rowa = rowl + 64;

    int tid = threadIdx.x;
    int wid = tid >> 5, lane = tid & 31;
    int r = lane >> 2, c = lane & 3, g = lane >> 2;
    int qt = blockIdx.x, h = blockIdx.y, b = blockIdx.z;
    int qbase = qt * 64;
    int wm = (wid & 3) * 16, wn = (wid >> 2) * 32;

    const float* qp  = Q  + (((size_t)(b * 16 + h) * 2048 + qbase) << 6);
    const float* kp0 = Kg + (((size_t)(b * 16 + h) * 2048) << 6);
    const float* vt0 = Vt + ((size_t)(b * 16 + h) * 64) * 2048;
    const int*   mp  = mask + ((size_t)b * 2048 + qbase) * 2048;

    // stage Q tile (cvt to tf32)
#pragma unroll
    for (int i = 0; i < 4; i++) {
        int lin = tid + i * 256;
        int row = lin >> 4, c4 = (lin & 15) << 2;
        float4 q4 = *(const float4*)&qp[row * 64 + c4];
        uint4 u;
        u.x = f2tf(q4.x); u.y = f2tf(q4.y); u.z = f2tf(q4.z); u.w = f2tf(q4.w);
        *(uint4*)&Qs[row * 68 + c4] = u;
    }
    if (tid < 64) { rowm[tid] = MINIT; rowl[tid] = 0.f; }

    float oacc[4][4];
#pragma unroll
    for (int nt = 0; nt < 4; nt++)
#pragma unroll
        for (int i = 0; i < 4; i++) oacc[nt][i] = 0.f;

    for (int kb = 0; kb < 2048; kb += 64) {
        __syncthreads();
        // stage K tile + Vt tile
#pragma unroll
        for (int i = 0; i < 4; i++) {
            int lin = tid + i * 256;
            int row = lin >> 4, c4 = (lin & 15) << 2;
            float4 k4 = *(const float4*)&kp0[(size_t)(kb + row) * 64 + c4];
            uint4 u;
            u.x = f2tf(k4.x); u.y = f2tf(k4.y); u.z = f2tf(k4.z); u.w = f2tf(k4.w);
            *(uint4*)&Ks[row * 68 + c4] = u;
            float4 v4 = *(const float4*)&vt0[(size_t)row * 2048 + kb + c4];
            uint4 v;
            v.x = f2tf(v4.x); v.y = f2tf(v4.y); v.z = f2tf(v4.z); v.w = f2tf(v4.w);
            *(uint4*)&Vs[row * 68 + c4] = v;
        }
        __syncthreads();

        // ---- scores = Q K^T * 0.125 ----
        {
            float sacc[4][4];
#pragma unroll
            for (int nt = 0; nt < 4; nt++)
#pragma unroll
                for (int i = 0; i < 4; i++) sacc[nt][i] = 0.f;
#pragma unroll
            for (int ks = 0; ks < 8; ks++) {
                int k8 = ks * 8;
                unsigned ua[4], ub[4][2];
                ua[0] = Qs[(wm + r) * 68 + k8 + c];
                ua[1] = Qs[(wm + r + 8) * 68 + k8 + c];
                ua[2] = Qs[(wm + r) * 68 + k8 + c + 4];
                ua[3] = Qs[(wm + r + 8) * 68 + k8 + c + 4];
#pragma unroll
                for (int nt = 0; nt < 4; nt++) {
                    int kv = wn + nt * 8 + g;
                    ub[nt][0] = Ks[kv * 68 + k8 + c];
                    ub[nt][1] = Ks[kv * 68 + k8 + c + 4];
                }
#pragma unroll
                for (int nt = 0; nt < 4; nt++) mma_tf32(sacc[nt], ua, ub[nt]);
            }
#pragma unroll
            for (int nt = 0; nt < 4; nt++) {
                int cc = wn + nt * 8 + 2 * c;
                *(float2*)&Ssf[(wm + r) * 68 + cc] =
                    make_float2(sacc[nt][0] * 0.125f, sacc[nt][1] * 0.125f);
                *(float2*)&Ssf[(wm + r + 8) * 68 + cc] =
                    make_float2(sacc[nt][2] * 0.125f, sacc[nt][3] * 0.125f);
            }
        }
        __syncthreads();

        // ---- online softmax: 4 lanes per row, 16 cols each ----
        {
            int srow = tid >> 2, q4 = tid & 3, jb = q4 * 16;
            const int* mrow = mp + (size_t)srow * 2048 + kb + jb;
            float mo = rowm[srow];
            float mx = mo;
            float sv[16];
#pragma unroll
            for (int jj = 0; jj < 16; jj += 4) {
                int4 mv = *(const int4*)&mrow[jj];
                float* sp = &Ssf[srow * 68 + jb + jj];
                sv[jj]     = mv.x ? sp[0] : NEGV;
                sv[jj + 1] = mv.y ? sp[1] : NEGV;
                sv[jj + 2] = mv.z ? sp[2] : NEGV;
                sv[jj + 3] = mv.w ? sp[3] : NEGV;
                mx = fmaxf(mx, fmaxf(fmaxf(sv[jj], sv[jj + 1]),
                                     fmaxf(sv[jj + 2], sv[jj + 3])));
            }
            mx = fmaxf(mx, __shfl_xor_sync(0xffffffffu, mx, 1));
            mx = fmaxf(mx, __shfl_xor_sync(0xffffffffu, mx, 2));
            float sum = 0.f;
#pragma unroll
            for (int jj = 0; jj < 16; jj++) {
                float p = __expf(sv[jj] - mx);
                unsigned up = f2tf(p);
                Ssu[srow * 68 + jb + jj] = up;
                sum += __uint_as_float(up);
            }
            sum += __shfl_xor_sync(0xffffffffu, sum, 1);
            sum += __shfl_xor_sync(0xffffffffu, sum, 2);
            if (q4 == 0) {
                float alpha = __expf(mo - mx);
                rowm[srow] = mx;
                rowl[srow] = rowl[srow] * alpha + sum;
                rowa[srow] = alpha;
            }
        }
        __syncthreads();

        // ---- O = O*alpha + P V ----
        {
            float a0 = rowa[wm + r], a8 = rowa[wm + r + 8];
#pragma unroll
            for (int nt = 0; nt < 4; nt++) {
                oacc[nt][0] *= a0; oacc[nt][1] *= a0;
                oacc[nt][2] *= a8; oacc[nt][3] *= a8;
            }
#pragma unroll
            for (int ks = 0; ks < 8; ks++) {
                int k8 = ks * 8;
                unsigned ua[4], ub[4][2];
                ua[0] = Ssu[(wm + r) * 68 + k8 + c];
                ua[1] = Ssu[(wm + r + 8) * 68 + k8 + c];
                ua[2] = Ssu[(wm + r) * 68 + k8 + c + 4];
                ua[3] = Ssu[(wm + r + 8) * 68 + k8 + c + 4];
#pragma unroll
                for (int nt = 0; nt < 4; nt++) {
                    int dv = wn + nt * 8 + g;
                    ub[nt][0] = Vs[dv * 68 + k8 + c];
                    ub[nt][1] = Vs[dv * 68 + k8 + c + 4];
                }
#pragma unroll
                for (int nt = 0; nt < 4; nt++) mma_tf32(oacc[nt], ua, ub[nt]);
            }
        }
    }

    // final normalize + write [B,S,H*64]
    float l0 = 1.f / rowl[wm + r], l8 = 1.f / rowl[wm + r + 8];
#pragma unroll
    for (int nt = 0; nt < 4; nt++) {
        int cc = h * 64 + wn + nt * 8 + 2 * c;
        int rowg = qbase + wm + r;
        *(float2*)&O[(size_t)(b * 2048 + rowg) * 1024 + cc] =
            make_float2(oacc[nt][0] * l0, oacc[nt][1] * l0);
        *(float2*)&O[(size_t)(b * 2048 + rowg + 8) * 1024 + cc] =
            make_float2(oacc[nt][2] * l8, oacc[nt][3] * l8);
    }
}

// ---------------------------------------------------------------------------
// residual + LayerNorm
// ---------------------------------------------------------------------------
__global__ void __launch_bounds__(256) ln_kernel(
    const float* __restrict__ Y, const float* __restrict__ R,
    const float* __restrict__ g, const float* __restrict__ bt,
    float* __restrict__ out)
{
    __shared__ float red[2][8];
    int row = blockIdx.x;
    int tid = threadIdx.x;
    int lane = tid & 31, wid = tid >> 5;

    float4 y4 = ((const float4*)(Y + (size_t)row * 1024))[tid];
    float4 r4 = ((const float4*)(R + (size_t)row * 1024))[tid];
    float x0 = y4.x + r4.x, x1 = y4.y + r4.y, x2 = y4.z + r4.z, x3 = y4.w + r4.w;

    float sum = x0 + x1 + x2 + x3;
    float sq  = x0 * x0 + x1 * x1 + x2 * x2 + x3 * x3;
#pragma unroll
    for (int off = 16; off > 0; off >>= 1) {
        sum += __shfl_xor_sync(0xffffffff, sum, off);
        sq  += __shfl_xor_sync(0xffffffff, sq,  off);
    }
    if (lane == 0) { red[0][wid] = sum; red[1][wid] = sq; }
    __syncthreads();
    if (tid == 0) {
        float ts = 0.f, tq = 0.f;
#pragma unroll
        for (int w = 0; w < 8; w++) { ts += red[0][w]; tq += red[1][w]; }
        red[0][0] = ts; red[1][0] = tq;
    }
    __syncthreads();
    float mu  = red[0][0] * (1.f / 1024.f);
    float var = red[1][0] * (1.f / 1024.f) - mu * mu;
    float rstd = rsqrtf(var + 1e-6f);

    float4 g4 = ((const float4*)g)[tid];
    float4 b4 = ((const float4*)bt)[tid];
    float4 o;
    o.x = (x0 - mu) * rstd * g4.x + b4.x;
    o.y = (x1 - mu) * rstd * g4.y + b4.y;
    o.z = (x2 - mu) * rstd * g4.z + b4.z;
    o.w = (x3 - mu) * rstd * g4.w + b4.w;
    ((float4*)(out + (size_t)row * 1024))[tid] = o;
}

// ---------------------------------------------------------------------------
extern "C" void kernel_launch(void* const* d_in, const int* in_sizes, int n_in,
                              void* d_out, int out_size)
{
    const float* query = (const float*)d_in[0];
    const float* key   = (const float*)d_in[1];
    const float* value = (const float*)d_in[2];
    const int*   mask  = (const int*)d_in[3];
    const float* w_qs  = (const float*)d_in[4];
    const float* w_ks  = (const float*)d_in[5];
    const float* w_vs  = (const float*)d_in[6];
    const float* w_out = (const float*)d_in[7];
    const float* ln_g  = (const float*)d_in[8];
    const float* ln_b  = (const float*)d_in[9];
    float* out = (float*)d_out;

    float *q, *k, *v, *attn, *y;
    cudaGetSymbolAddress((void**)&q,    g_q);
    cudaGetSymbolAddress((void**)&k,    g_k);
    cudaGetSymbolAddress((void**)&v,    g_v);
    cudaGetSymbolAddress((void**)&attn, g_attn);
    cudaGetSymbolAddress((void**)&y,    g_y);

    dim3 gg(8, 64);   // N/128, M/128 for M=8192, N=1024

    gemm_tc<<<gg, 256>>>(query, w_qs, q, 8192, 1024, 1024, 1);
    gemm_tc<<<gg, 256>>>(key,   w_ks, k, 8192, 1024, 1024, 1);
    gemm_tc<<<gg, 256>>>(value, w_vs, v, 8192, 1024, 1024, 2);

    cudaFuncSetAttribute(attn_tc,
                         cudaFuncAttributeMaxDynamicSharedMemorySize,
                         ATTN_SMEM);
    attn_tc<<<dim3(32, 16, 4), 256, ATTN_SMEM>>>(q, k, v, mask, attn);

    gemm_tc<<<gg, 256>>>(attn, w_out, y, 8192, 1024, 1024, 0);

    ln_kernel<<<8192, 256>>>(y, query, ln_g, ln_b, out);
}

// round 3
// speedup vs baseline: 2.8699x; 1.3073x over previous
#include <cuda_runtime.h>

// ---------------------------------------------------------------------------
// MultiHeadedAttention: B=4, S=2048, D_MODEL=1024, H=16, DK=DV=64
// Round 3: bigger warp tiles (64x32) in attention (LDS/mma 3.0 -> 1.5),
//          128-row Q tiles, per-thread-row softmax, GEMM register
//          double-buffering.
// ---------------------------------------------------------------------------

#define NEGV (-1e9f)
#define MINIT (-1e38f)

__device__ float g_q[4 * 16 * 2048 * 64];
__device__ float g_k[4 * 16 * 2048 * 64];
__device__ float g_v[4 * 16 * 2048 * 64];   // V^T per head: [B,H,64,2048]
__device__ float g_attn[8192 * 1024];
__device__ float g_y[8192 * 1024];

__device__ __forceinline__ unsigned f2tf(float f) {
    unsigned u;
    asm("cvt.rna.tf32.f32 %0, %1;" : "=r"(u) : "f"(f));
    return u;
}

__device__ __forceinline__ void mma_tf32(float c[4], const unsigned a[4],
                                         const unsigned b[2]) {
    asm volatile(
        "mma.sync.aligned.m16n8k8.row.col.f32.tf32.tf32.f32 "
        "{%0,%1,%2,%3}, {%4,%5,%6,%7}, {%8,%9}, {%0,%1,%2,%3};"
        : "+f"(c[0]), "+f"(c[1]), "+f"(c[2]), "+f"(c[3])
        : "r"(a[0]), "r"(a[1]), "r"(a[2]), "r"(a[3]), "r"(b[0]), "r"(b[1]));
}

// ---------------------------------------------------------------------------
// tf32 GEMM with register double-buffering. 128x128 tile, k-tile 32,
// 256 threads (8 warps, warp tile 64x32).
// mode 0: row-major out.  mode 1: [B,H,S,64].  mode 2: V^T [B,H,64,S].
// ---------------------------------------------------------------------------
__global__ void __launch_bounds__(256) gemm_tc(
    const float* __restrict__ A, const float* __restrict__ B,
    float* __restrict__ C, int M, int N, int K, int mode)
{
    __shared__ unsigned As[128 * 36];
    __shared__ unsigned Bs[32 * 132];

    int tid = threadIdx.x;
    int wid = tid >> 5, lane = tid & 31;
    int r = lane >> 2, c = lane & 3, g = lane >> 2;
    int m0 = blockIdx.y * 128, n0 = blockIdx.x * 128;
    int wm = (wid & 1) * 64, wn = (wid >> 1) * 32;

    // load indices
    int arow[4], acol[4], brow[4], bcol[4];
#pragma unroll
    for (int i = 0; i < 4; i++) {
        int lin = tid + i * 256;
        arow[i] = lin >> 3;  acol[i] = (lin & 7) << 2;    // A 128x32
        brow[i] = lin >> 5;  bcol[i] = (lin & 31) << 2;   // B 32x128
    }

    float acc[4][4][4];
#pragma unroll
    for (int mt = 0; mt < 4; mt++)
#pragma unroll
        for (int nt = 0; nt < 4; nt++)
#pragma unroll
            for (int i = 0; i < 4; i++) acc[mt][nt][i] = 0.f;

    float4 pa[4], pb[4];
#pragma unroll
    for (int i = 0; i < 4; i++) {
        pa[i] = *(const float4*)&A[(size_t)(m0 + arow[i]) * K + acol[i]];
        pb[i] = *(const float4*)&B[(size_t)brow[i] * N + n0 + bcol[i]];
    }

    for (int k0 = 0; k0 < K; k0 += 32) {
        __syncthreads();
#pragma unroll
        for (int i = 0; i < 4; i++) {
            uint4 ua = {f2tf(pa[i].x), f2tf(pa[i].y), f2tf(pa[i].z), f2tf(pa[i].w)};
            *(uint4*)&As[arow[i] * 36 + acol[i]] = ua;
            uint4 ub = {f2tf(pb[i].x), f2tf(pb[i].y), f2tf(pb[i].z), f2tf(pb[i].w)};
            *(uint4*)&Bs[brow[i] * 132 + bcol[i]] = ub;
        }
        if (k0 + 32 < K) {
#pragma unroll
            for (int i = 0; i < 4; i++) {
                pa[i] = *(const float4*)&A[(size_t)(m0 + arow[i]) * K + k0 + 32 + acol[i]];
                pb[i] = *(const float4*)&B[(size_t)(k0 + 32 + brow[i]) * N + n0 + bcol[i]];
            }
        }
        __syncthreads();

#pragma unroll
        for (int ks = 0; ks < 4; ks++) {
            int k8 = ks * 8;
            unsigned ua[4][4], ub[4][2];
#pragma unroll
            for (int mt = 0; mt < 4; mt++) {
                int rr = wm + mt * 16 + r;
                ua[mt][0] = As[rr * 36 + k8 + c];
                ua[mt][1] = As[(rr + 8) * 36 + k8 + c];
                ua[mt][2] = As[rr * 36 + k8 + c + 4];
                ua[mt][3] = As[(rr + 8) * 36 + k8 + c + 4];
            }
#pragma unroll
            for (int nt = 0; nt < 4; nt++) {
                int cn = wn + nt * 8 + g;
                ub[nt][0] = Bs[(k8 + c) * 132 + cn];
                ub[nt][1] = Bs[(k8 + c + 4) * 132 + cn];
            }
#pragma unroll
            for (int mt = 0; mt < 4; mt++)
#pragma unroll
                for (int nt = 0; nt < 4; nt++)
                    mma_tf32(acc[mt][nt], ua[mt], ub[nt]);
        }
    }

#pragma unroll
    for (int mt = 0; mt < 4; mt++) {
#pragma unroll
        for (int nt = 0; nt < 4; nt++) {
            int rr = m0 + wm + mt * 16 + r;
            int cc = n0 + wn + nt * 8 + 2 * c;
            float* a4 = acc[mt][nt];
            if (mode == 0) {
                *(float2*)&C[(size_t)rr * N + cc] = make_float2(a4[0], a4[1]);
                *(float2*)&C[(size_t)(rr + 8) * N + cc] = make_float2(a4[2], a4[3]);
            } else if (mode == 1) {
                int b = rr >> 11, s = rr & 2047;
                int h = cc >> 6, d = cc & 63;
                size_t idx = (((size_t)(b * 16 + h) * 2048 + s) << 6) + d;
                *(float2*)&C[idx] = make_float2(a4[0], a4[1]);
                int b2 = (rr + 8) >> 11, s2 = (rr + 8) & 2047;
                size_t idx2 = (((size_t)(b2 * 16 + h) * 2048 + s2) << 6) + d;
                *(float2*)&C[idx2] = make_float2(a4[2], a4[3]);
            } else {  // V^T [B,H,64,2048]
                int b = rr >> 11, s = rr & 2047;
                int h = cc >> 6, d = cc & 63;
                size_t base = ((size_t)(b * 16 + h) * 64 + d) * 2048;
                C[base + s] = a4[0];
                C[base + 2048 + s] = a4[1];
                int b2 = (rr + 8) >> 11, s2 = (rr + 8) & 2047;
                size_t base2 = ((size_t)(b2 * 16 + h) * 64 + d) * 2048;
                C[base2 + s2] = a4[2];
                C[base2 + 2048 + s2] = a4[3];
            }
        }
    }
}

// ---------------------------------------------------------------------------
// Flash attention. grid = (S/128, H, B), 128 threads (4 warps, warp 64x32).
// Q,K in [B,H,S,64]; V^T in [B,H,64,S]; out -> [B,S,H*64].
// SMEM: Qs[128*68] Ks[64*68] Vs[64*68] Ssf[128*68] + rowm/rowl/rowa[128].
// ---------------------------------------------------------------------------
#define ATTN_SMEM ((128 * 68 + 64 * 68 + 64 * 68 + 128 * 68 + 384) * 4)

__global__ void __launch_bounds__(128) attn_tc(
    const float* __restrict__ Q, const float* __restrict__ Kg,
    const float* __restrict__ Vt, const int* __restrict__ mask,
    float* __restrict__ O)
{
    extern __shared__ unsigned smu[];
    unsigned* Qs = smu;                    // 128 x 68
    unsigned* Ks = Qs + 128 * 68;          // 64 x 68
    unsigned* Vs = Ks + 64 * 68;           // 64 x 68 (V^T: [dv][kpos])
    float*    Ssf = (float*)(Vs + 64 * 68);// 128 x 68
    unsigned* Ssu = (unsigned*)Ssf;
    float* rowm = Ssf + 128 * 68;
    float* rowl = rowm + 128;
    float* rowa = rowl + 128;

    int tid = threadIdx.x;
    int wid = tid >> 5, lane = tid & 31;
    int r = lane >> 2, c = lane & 3, g = lane >> 2;
    int qt = blockIdx.x, h = blockIdx.y, b = blockIdx.z;
    int qbase = qt * 128;
    int wm = (wid & 1) * 64, wn = (wid >> 1) * 32;

    const float* qp  = Q  + (((size_t)(b * 16 + h) * 2048 + qbase) << 6);
    const float* kp0 = Kg + (((size_t)(b * 16 + h) * 2048) << 6);
    const float* vt0 = Vt + ((size_t)(b * 16 + h) * 64) * 2048;
    const int*   mrow = mask + ((size_t)b * 2048 + qbase + tid) * 2048;

    // stage Q tile (128x64 -> tf32)
#pragma unroll
    for (int i = 0; i < 16; i++) {
        int lin = tid + i * 128;
        int row = lin >> 4, c4 = (lin & 15) << 2;
        float4 q4 = *(const float4*)&qp[row * 64 + c4];
        uint4 u = {f2tf(q4.x), f2tf(q4.y), f2tf(q4.z), f2tf(q4.w)};
        *(uint4*)&Qs[row * 68 + c4] = u;
    }
    rowm[tid] = MINIT;
    rowl[tid] = 0.f;

    float oacc[4][4][4];
#pragma unroll
    for (int mt = 0; mt < 4; mt++)
#pragma unroll
        for (int nt = 0; nt < 4; nt++)
#pragma unroll
            for (int i = 0; i < 4; i++) oacc[mt][nt][i] = 0.f;

    for (int kb = 0; kb < 2048; kb += 64) {
        __syncthreads();
        // stage K tile + V^T tile (each 64x64)
#pragma unroll
        for (int i = 0; i < 8; i++) {
            int lin = tid + i * 128;
            int row = lin >> 4, c4 = (lin & 15) << 2;
            float4 k4 = *(const float4*)&kp0[(size_t)(kb + row) * 64 + c4];
            uint4 uk = {f2tf(k4.x), f2tf(k4.y), f2tf(k4.z), f2tf(k4.w)};
            *(uint4*)&Ks[row * 68 + c4] = uk;
            float4 v4 = *(const float4*)&vt0[(size_t)row * 2048 + kb + c4];
            uint4 uv = {f2tf(v4.x), f2tf(v4.y), f2tf(v4.z), f2tf(v4.w)};
            *(uint4*)&Vs[row * 68 + c4] = uv;
        }
        __syncthreads();

        // ---- S = Q K^T * 0.125 ----
        {
            float sacc[4][4][4];
#pragma unroll
            for (int mt = 0; mt < 4; mt++)
#pragma unroll
                for (int nt = 0; nt < 4; nt++)
#pragma unroll
                    for (int i = 0; i < 4; i++) sacc[mt][nt][i] = 0.f;

#pragma unroll
            for (int ks = 0; ks < 8; ks++) {
                int k8 = ks * 8;
                unsigned ua[4][4], ub[4][2];
#pragma unroll
                for (int mt = 0; mt < 4; mt++) {
                    int rr = wm + mt * 16 + r;
                    ua[mt][0] = Qs[rr * 68 + k8 + c];
                    ua[mt][1] = Qs[(rr + 8) * 68 + k8 + c];
                    ua[mt][2] = Qs[rr * 68 + k8 + c + 4];
                    ua[mt][3] = Qs[(rr + 8) * 68 + k8 + c + 4];
                }
#pragma unroll
                for (int nt = 0; nt < 4; nt++) {
                    int kv = wn + nt * 8 + g;
                    ub[nt][0] = Ks[kv * 68 + k8 + c];
                    ub[nt][1] = Ks[kv * 68 + k8 + c + 4];
                }
#pragma unroll
                for (int mt = 0; mt < 4; mt++)
#pragma unroll
                    for (int nt = 0; nt < 4; nt++)
                        mma_tf32(sacc[mt][nt], ua[mt], ub[nt]);
            }
#pragma unroll
            for (int mt = 0; mt < 4; mt++)
#pragma unroll
                for (int nt = 0; nt < 4; nt++) {
                    int rr = wm + mt * 16 + r;
                    int cc = wn + nt * 8 + 2 * c;
                    float* s4 = sacc[mt][nt];
                    *(float2*)&Ssf[rr * 68 + cc] =
                        make_float2(s4[0] * 0.125f, s4[1] * 0.125f);
                    *(float2*)&Ssf[(rr + 8) * 68 + cc] =
                        make_float2(s4[2] * 0.125f, s4[3] * 0.125f);
                }
        }
        __syncthreads();

        // ---- online softmax: one thread per row ----
        {
            const int* mp = mrow + kb;
            float mo = rowm[tid];
            float mx = mo;
            float sv[64];
#pragma unroll
            for (int j4 = 0; j4 < 16; j4++) {
                float4 s4 = *(const float4*)&Ssf[tid * 68 + j4 * 4];
                int4 m4 = *(const int4*)&mp[j4 * 4];
                float v0 = m4.x ? s4.x : NEGV;
                float v1 = m4.y ? s4.y : NEGV;
                float v2 = m4.z ? s4.z : NEGV;
                float v3 = m4.w ? s4.w : NEGV;
                sv[j4 * 4 + 0] = v0; sv[j4 * 4 + 1] = v1;
                sv[j4 * 4 + 2] = v2; sv[j4 * 4 + 3] = v3;
                mx = fmaxf(mx, fmaxf(fmaxf(v0, v1), fmaxf(v2, v3)));
            }
            float alpha = __expf(mo - mx);
            float sum = 0.f;
#pragma unroll
            for (int j4 = 0; j4 < 16; j4++) {
                uint4 u;
                u.x = f2tf(__expf(sv[j4 * 4 + 0] - mx));
                u.y = f2tf(__expf(sv[j4 * 4 + 1] - mx));
                u.z = f2tf(__expf(sv[j4 * 4 + 2] - mx));
                u.w = f2tf(__expf(sv[j4 * 4 + 3] - mx));
                sum += __uint_as_float(u.x) + __uint_as_float(u.y) +
                       __uint_as_float(u.z) + __uint_as_float(u.w);
                *(uint4*)&Ssu[tid * 68 + j4 * 4] = u;
            }
            rowm[tid] = mx;
            rowl[tid] = rowl[tid] * alpha + sum;
            rowa[tid] = alpha;
        }
        __syncthreads();

        // ---- O = O*alpha + P V ----
        {
#pragma unroll
            for (int mt = 0; mt < 4; mt++) {
                float a0 = rowa[wm + mt * 16 + r];
                float a8 = rowa[wm + mt * 16 + r + 8];
#pragma unroll
                for (int nt = 0; nt < 4; nt++) {
                    oacc[mt][nt][0] *= a0; oacc[mt][nt][1] *= a0;
                    oacc[mt][nt][2] *= a8; oacc[mt][nt][3] *= a8;
                }
            }
#pragma unroll
            for (int ks = 0; ks < 8; ks++) {
                int k8 = ks * 8;
                unsigned ua[4][4], ub[4][2];
#pragma unroll
                for (int mt = 0; mt < 4; mt++) {
                    int rr = wm + mt * 16 + r;
                    ua[mt][0] = Ssu[rr * 68 + k8 + c];
                    ua[mt][1] = Ssu[(rr + 8) * 68 + k8 + c];
                    ua[mt][2] = Ssu[rr * 68 + k8 + c + 4];
                    ua[mt][3] = Ssu[(rr + 8) * 68 + k8 + c + 4];
                }
#pragma unroll
                for (int nt = 0; nt < 4; nt++) {
                    int dv = wn + nt * 8 + g;
                    ub[nt][0] = Vs[dv * 68 + k8 + c];
                    ub[nt][1] = Vs[dv * 68 + k8 + c + 4];
                }
#pragma unroll
                for (int mt = 0; mt < 4; mt++)
#pragma unroll
                    for (int nt = 0; nt < 4; nt++)
                        mma_tf32(oacc[mt][nt], ua[mt], ub[nt]);
            }
        }
    }

    // final normalize + write [B,S,H*64]
#pragma unroll
    for (int mt = 0; mt < 4; mt++) {
        float l0 = 1.f / rowl[wm + mt * 16 + r];
        float l8 = 1.f / rowl[wm + mt * 16 + r + 8];
        int rowg = qbase + wm + mt * 16 + r;
#pragma unroll
        for (int nt = 0; nt < 4; nt++) {
            int cc = h * 64 + wn + nt * 8 + 2 * c;
            *(float2*)&O[(size_t)(b * 2048 + rowg) * 1024 + cc] =
                make_float2(oacc[mt][nt][0] * l0, oacc[mt][nt][1] * l0);
            *(float2*)&O[(size_t)(b * 2048 + rowg + 8) * 1024 + cc] =
                make_float2(oacc[mt][nt][2] * l8, oacc[mt][nt][3] * l8);
        }
    }
}

// ---------------------------------------------------------------------------
// residual + LayerNorm
// ---------------------------------------------------------------------------
__global__ void __launch_bounds__(256) ln_kernel(
    const float* __restrict__ Y, const float* __restrict__ R,
    const float* __restrict__ g, const float* __restrict__ bt,
    float* __restrict__ out)
{
    __shared__ float red[2][8];
    int row = blockIdx.x;
    int tid = threadIdx.x;
    int lane = tid & 31, wid = tid >> 5;

    float4 y4 = ((const float4*)(Y + (size_t)row * 1024))[tid];
    float4 r4 = ((const float4*)(R + (size_t)row * 1024))[tid];
    float x0 = y4.x + r4.x, x1 = y4.y + r4.y, x2 = y4.z + r4.z, x3 = y4.w + r4.w;

    float sum = x0 + x1 + x2 + x3;
    float sq  = x0 * x0 + x1 * x1 + x2 * x2 + x3 * x3;
#pragma unroll
    for (int off = 16; off > 0; off >>= 1) {
        sum += __shfl_xor_sync(0xffffffff, sum, off);
        sq  += __shfl_xor_sync(0xffffffff, sq,  off);
    }
    if (lane == 0) { red[0][wid] = sum; red[1][wid] = sq; }
    __syncthreads();
    if (tid == 0) {
        float ts = 0.f, tq = 0.f;
#pragma unroll
        for (int w = 0; w < 8; w++) { ts += red[0][w]; tq += red[1][w]; }
        red[0][0] = ts; red[1][0] = tq;
    }
    __syncthreads();
    float mu  = red[0][0] * (1.f / 1024.f);
    float var = red[1][0] * (1.f / 1024.f) - mu * mu;
    float rstd = rsqrtf(var + 1e-6f);

    float4 g4 = ((const float4*)g)[tid];
    float4 b4 = ((const float4*)bt)[tid];
    float4 o;
    o.x = (x0 - mu) * rstd * g4.x + b4.x;
    o.y = (x1 - mu) * rstd * g4.y + b4.y;
    o.z = (x2 - mu) * rstd * g4.z + b4.z;
    o.w = (x3 - mu) * rstd * g4.w + b4.w;
    ((float4*)(out + (size_t)row * 1024))[tid] = o;
}

// ---------------------------------------------------------------------------
extern "C" void kernel_launch(void* const* d_in, const int* in_sizes, int n_in,
                              void* d_out, int out_size)
{
    const float* query = (const float*)d_in[0];
    const float* key   = (const float*)d_in[1];
    const float* value = (const float*)d_in[2];
    const int*   mask  = (const int*)d_in[3];
    const float* w_qs  = (const float*)d_in[4];
    const float* w_ks  = (const float*)d_in[5];
    const float* w_vs  = (const float*)d_in[6];
    const float* w_out = (const float*)d_in[7];
    const float* ln_g  = (const float*)d_in[8];
    const float* ln_b  = (const float*)d_in[9];
    float* out = (float*)d_out;

    float *q, *k, *v, *attn, *y;
    cudaGetSymbolAddress((void**)&q,    g_q);
    cudaGetSymbolAddress((void**)&k,    g_k);
    cudaGetSymbolAddress((void**)&v,    g_v);
    cudaGetSymbolAddress((void**)&attn, g_attn);
    cudaGetSymbolAddress((void**)&y,    g_y);

    dim3 gg(8, 64);   // N/128, M/128 for M=8192, N=1024

    gemm_tc<<<gg, 256>>>(query, w_qs, q, 8192, 1024, 1024, 1);
    gemm_tc<<<gg, 256>>>(key,   w_ks, k, 8192, 1024, 1024, 1);
    gemm_tc<<<gg, 256>>>(value, w_vs, v, 8192, 1024, 1024, 2);

    cudaFuncSetAttribute(attn_tc,
                         cudaFuncAttributeMaxDynamicSharedMemorySize,
                         ATTN_SMEM);
    attn_tc<<<dim3(16, 16, 4), 128, ATTN_SMEM>>>(q, k, v, mask, attn);

    gemm_tc<<<gg, 256>>>(attn, w_out, y, 8192, 1024, 1024, 0);

    ln_kernel<<<8192, 256>>>(y, query, ln_g, ln_b, out);
}

// round 4
// speedup vs baseline: 2.8700x; 1.0000x over previous
#include <cuda_runtime.h>

// ---------------------------------------------------------------------------
// MultiHeadedAttention: B=4, S=2048, D_MODEL=1024, H=16, DK=DV=64
// Round 3: bigger warp tiles (64x32) in attention (LDS/mma 3.0 -> 1.5),
//          128-row Q tiles, per-thread-row softmax, GEMM register
//          double-buffering.
// ---------------------------------------------------------------------------

#define NEGV (-1e9f)
#define MINIT (-1e38f)

__device__ float g_q[4 * 16 * 2048 * 64];
__device__ float g_k[4 * 16 * 2048 * 64];
__device__ float g_v[4 * 16 * 2048 * 64];   // V^T per head: [B,H,64,2048]
__device__ float g_attn[8192 * 1024];
__device__ float g_y[8192 * 1024];

__device__ __forceinline__ unsigned f2tf(float f) {
    unsigned u;
    asm("cvt.rna.tf32.f32 %0, %1;" : "=r"(u) : "f"(f));
    return u;
}

__device__ __forceinline__ void mma_tf32(float c[4], const unsigned a[4],
                                         const unsigned b[2]) {
    asm volatile(
        "mma.sync.aligned.m16n8k8.row.col.f32.tf32.tf32.f32 "
        "{%0,%1,%2,%3}, {%4,%5,%6,%7}, {%8,%9}, {%0,%1,%2,%3};"
        : "+f"(c[0]), "+f"(c[1]), "+f"(c[2]), "+f"(c[3])
        : "r"(a[0]), "r"(a[1]), "r"(a[2]), "r"(a[3]), "r"(b[0]), "r"(b[1]));
}

// ---------------------------------------------------------------------------
// tf32 GEMM with register double-buffering. 128x128 tile, k-tile 32,
// 256 threads (8 warps, warp tile 64x32).
// mode 0: row-major out.  mode 1: [B,H,S,64].  mode 2: V^T [B,H,64,S].
// ---------------------------------------------------------------------------
__global__ void __launch_bounds__(256) gemm_tc(
    const float* __restrict__ A, const float* __restrict__ B,
    float* __restrict__ C, int M, int N, int K, int mode)
{
    __shared__ unsigned As[128 * 36];
    __shared__ unsigned Bs[32 * 132];

    int tid = threadIdx.x;
    int wid = tid >> 5, lane = tid & 31;
    int r = lane >> 2, c = lane & 3, g = lane >> 2;
    int m0 = blockIdx.y * 128, n0 = blockIdx.x * 128;
    int wm = (wid & 1) * 64, wn = (wid >> 1) * 32;

    // load indices
    int arow[4], acol[4], brow[4], bcol[4];
#pragma unroll
    for (int i = 0; i < 4; i++) {
        int lin = tid + i * 256;
        arow[i] = lin >> 3;  acol[i] = (lin & 7) << 2;    // A 128x32
        brow[i] = lin >> 5;  bcol[i] = (lin & 31) << 2;   // B 32x128
    }

    float acc[4][4][4];
#pragma unroll
    for (int mt = 0; mt < 4; mt++)
#pragma unroll
        for (int nt = 0; nt < 4; nt++)
#pragma unroll
            for (int i = 0; i < 4; i++) acc[mt][nt][i] = 0.f;

    float4 pa[4], pb[4];
#pragma unroll
    for (int i = 0; i < 4; i++) {
        pa[i] = *(const float4*)&A[(size_t)(m0 + arow[i]) * K + acol[i]];
        pb[i] = *(const float4*)&B[(size_t)brow[i] * N + n0 + bcol[i]];
    }

    for (int k0 = 0; k0 < K; k0 += 32) {
        __syncthreads();
#pragma unroll
        for (int i = 0; i < 4; i++) {
            uint4 ua = {f2tf(pa[i].x), f2tf(pa[i].y), f2tf(pa[i].z), f2tf(pa[i].w)};
            *(uint4*)&As[arow[i] * 36 + acol[i]] = ua;
            uint4 ub = {f2tf(pb[i].x), f2tf(pb[i].y), f2tf(pb[i].z), f2tf(pb[i].w)};
            *(uint4*)&Bs[brow[i] * 132 + bcol[i]] = ub;
        }
        if (k0 + 32 < K) {
#pragma unroll
            for (int i = 0; i < 4; i++) {
                pa[i] = *(const float4*)&A[(size_t)(m0 + arow[i]) * K + k0 + 32 + acol[i]];
                pb[i] = *(const float4*)&B[(size_t)(k0 + 32 + brow[i]) * N + n0 + bcol[i]];
            }
        }
        __syncthreads();

#pragma unroll
        for (int ks = 0; ks < 4; ks++) {
            int k8 = ks * 8;
            unsigned ua[4][4], ub[4][2];
#pragma unroll
            for (int mt = 0; mt < 4; mt++) {
                int rr = wm + mt * 16 + r;
                ua[mt][0] = As[rr * 36 + k8 + c];
                ua[mt][1] = As[(rr + 8) * 36 + k8 + c];
                ua[mt][2] = As[rr * 36 + k8 + c + 4];
                ua[mt][3] = As[(rr + 8) * 36 + k8 + c + 4];
            }
#pragma unroll
            for (int nt = 0; nt < 4; nt++) {
                int cn = wn + nt * 8 + g;
                ub[nt][0] = Bs[(k8 + c) * 132 + cn];
                ub[nt][1] = Bs[(k8 + c + 4) * 132 + cn];
            }
#pragma unroll
            for (int mt = 0; mt < 4; mt++)
#pragma unroll
                for (int nt = 0; nt < 4; nt++)
                    mma_tf32(acc[mt][nt], ua[mt], ub[nt]);
        }
    }

#pragma unroll
    for (int mt = 0; mt < 4; mt++) {
#pragma unroll
        for (int nt = 0; nt < 4; nt++) {
            int rr = m0 + wm + mt * 16 + r;
            int cc = n0 + wn + nt * 8 + 2 * c;
            float* a4 = acc[mt][nt];
            if (mode == 0) {
                *(float2*)&C[(size_t)rr * N + cc] = make_float2(a4[0], a4[1]);
                *(float2*)&C[(size_t)(rr + 8) * N + cc] = make_float2(a4[2], a4[3]);
            } else if (mode == 1) {
                int b = rr >> 11, s = rr & 2047;
                int h = cc >> 6, d = cc & 63;
                size_t idx = (((size_t)(b * 16 + h) * 2048 + s) << 6) + d;
                *(float2*)&C[idx] = make_float2(a4[0], a4[1]);
                int b2 = (rr + 8) >> 11, s2 = (rr + 8) & 2047;
                size_t idx2 = (((size_t)(b2 * 16 + h) * 2048 + s2) << 6) + d;
                *(float2*)&C[idx2] = make_float2(a4[2], a4[3]);
            } else {  // V^T [B,H,64,2048]
                int b = rr >> 11, s = rr & 2047;
                int h = cc >> 6, d = cc & 63;
                size_t base = ((size_t)(b * 16 + h) * 64 + d) * 2048;
                C[base + s] = a4[0];
                C[base + 2048 + s] = a4[1];
                int b2 = (rr + 8) >> 11, s2 = (rr + 8) & 2047;
                size_t base2 = ((size_t)(b2 * 16 + h) * 64 + d) * 2048;
                C[base2 + s2] = a4[2];
                C[base2 + 2048 + s2] = a4[3];
            }
        }
    }
}

// ---------------------------------------------------------------------------
// Flash attention. grid = (S/128, H, B), 128 threads (4 warps, warp 64x32).
// Q,K in [B,H,S,64]; V^T in [B,H,64,S]; out -> [B,S,H*64].
// SMEM: Qs[128*68] Ks[64*68] Vs[64*68] Ssf[128*68] + rowm/rowl/rowa[128].
// ---------------------------------------------------------------------------
#define ATTN_SMEM ((128 * 68 + 64 * 68 + 64 * 68 + 128 * 68 + 384) * 4)

__global__ void __launch_bounds__(128) attn_tc(
    const float* __restrict__ Q, const float* __restrict__ Kg,
    const float* __restrict__ Vt, const int* __restrict__ mask,
    float* __restrict__ O)
{
    extern __shared__ unsigned smu[];
    unsigned* Qs = smu;                    // 128 x 68
    unsigned* Ks = Qs + 128 * 68;          // 64 x 68
    unsigned* Vs = Ks + 64 * 68;           // 64 x 68 (V^T: [dv][kpos])
    float*    Ssf = (float*)(Vs + 64 * 68);// 128 x 68
    unsigned* Ssu = (unsigned*)Ssf;
    float* rowm = Ssf + 128 * 68;
    float* rowl = rowm + 128;
    float* rowa = rowl + 128;

    int tid = threadIdx.x;
    int wid = tid >> 5, lane = tid & 31;
    int r = lane >> 2, c = lane & 3, g = lane >> 2;
    int qt = blockIdx.x, h = blockIdx.y, b = blockIdx.z;
    int qbase = qt * 128;
    int wm = (wid & 1) * 64, wn = (wid >> 1) * 32;

    const float* qp  = Q  + (((size_t)(b * 16 + h) * 2048 + qbase) << 6);
    const float* kp0 = Kg + (((size_t)(b * 16 + h) * 2048) << 6);
    const float* vt0 = Vt + ((size_t)(b * 16 + h) * 64) * 2048;
    const int*   mrow = mask + ((size_t)b * 2048 + qbase + tid) * 2048;

    // stage Q tile (128x64 -> tf32)
#pragma unroll
    for (int i = 0; i < 16; i++) {
        int lin = tid + i * 128;
        int row = lin >> 4, c4 = (lin & 15) << 2;
        float4 q4 = *(const float4*)&qp[row * 64 + c4];
        uint4 u = {f2tf(q4.x), f2tf(q4.y), f2tf(q4.z), f2tf(q4.w)};
        *(uint4*)&Qs[row * 68 + c4] = u;
    }
    rowm[tid] = MINIT;
    rowl[tid] = 0.f;

    float oacc[4][4][4];
#pragma unroll
    for (int mt = 0; mt < 4; mt++)
#pragma unroll
        for (int nt = 0; nt < 4; nt++)
#pragma unroll
            for (int i = 0; i < 4; i++) oacc[mt][nt][i] = 0.f;

    for (int kb = 0; kb < 2048; kb += 64) {
        __syncthreads();
        // stage K tile + V^T tile (each 64x64)
#pragma unroll
        for (int i = 0; i < 8; i++) {
            int lin = tid + i * 128;
            int row = lin >> 4, c4 = (lin & 15) << 2;
            float4 k4 = *(const float4*)&kp0[(size_t)(kb + row) * 64 + c4];
            uint4 uk = {f2tf(k4.x), f2tf(k4.y), f2tf(k4.z), f2tf(k4.w)};
            *(uint4*)&Ks[row * 68 + c4] = uk;
            float4 v4 = *(const float4*)&vt0[(size_t)row * 2048 + kb + c4];
            uint4 uv = {f2tf(v4.x), f2tf(v4.y), f2tf(v4.z), f2tf(v4.w)};
            *(uint4*)&Vs[row * 68 + c4] = uv;
        }
        __syncthreads();

        // ---- S = Q K^T * 0.125 ----
        {
            float sacc[4][4][4];
#pragma unroll
            for (int mt = 0; mt < 4; mt++)
#pragma unroll
                for (int nt = 0; nt < 4; nt++)
#pragma unroll
                    for (int i = 0; i < 4; i++) sacc[mt][nt][i] = 0.f;

#pragma unroll
            for (int ks = 0; ks < 8; ks++) {
                int k8 = ks * 8;
                unsigned ua[4][4], ub[4][2];
#pragma unroll
                for (int mt = 0; mt < 4; mt++) {
                    int rr = wm + mt * 16 + r;
                    ua[mt][0] = Qs[rr * 68 + k8 + c];
                    ua[mt][1] = Qs[(rr + 8) * 68 + k8 + c];
                    ua[mt][2] = Qs[rr * 68 + k8 + c + 4];
                    ua[mt][3] = Qs[(rr + 8) * 68 + k8 + c + 4];
                }
#pragma unroll
                for (int nt = 0; nt < 4; nt++) {
                    int kv = wn + nt * 8 + g;
                    ub[nt][0] = Ks[kv * 68 + k8 + c];
                    ub[nt][1] = Ks[kv * 68 + k8 + c + 4];
                }
#pragma unroll
                for (int mt = 0; mt < 4; mt++)
#pragma unroll
                    for (int nt = 0; nt < 4; nt++)
                        mma_tf32(sacc[mt][nt], ua[mt], ub[nt]);
            }
#pragma unroll
            for (int mt = 0; mt < 4; mt++)
#pragma unroll
                for (int nt = 0; nt < 4; nt++) {
                    int rr = wm + mt * 16 + r;
                    int cc = wn + nt * 8 + 2 * c;
                    float* s4 = sacc[mt][nt];
                    *(float2*)&Ssf[rr * 68 + cc] =
                        make_float2(s4[0] * 0.125f, s4[1] * 0.125f);
                    *(float2*)&Ssf[(rr + 8) * 68 + cc] =
                        make_float2(s4[2] * 0.125f, s4[3] * 0.125f);
                }
        }
        __syncthreads();

        // ---- online softmax: one thread per row ----
        {
            const int* mp = mrow + kb;
            float mo = rowm[tid];
            float mx = mo;
            float sv[64];
#pragma unroll
            for (int j4 = 0; j4 < 16; j4++) {
                float4 s4 = *(const float4*)&Ssf[tid * 68 + j4 * 4];
                int4 m4 = *(const int4*)&mp[j4 * 4];
                float v0 = m4.x ? s4.x : NEGV;
                float v1 = m4.y ? s4.y : NEGV;
                float v2 = m4.z ? s4.z : NEGV;
                float v3 = m4.w ? s4.w : NEGV;
                sv[j4 * 4 + 0] = v0; sv[j4 * 4 + 1] = v1;
                sv[j4 * 4 + 2] = v2; sv[j4 * 4 + 3] = v3;
                mx = fmaxf(mx, fmaxf(fmaxf(v0, v1), fmaxf(v2, v3)));
            }
            float alpha = __expf(mo - mx);
            float sum = 0.f;
#pragma unroll
            for (int j4 = 0; j4 < 16; j4++) {
                uint4 u;
                u.x = f2tf(__expf(sv[j4 * 4 + 0] - mx));
                u.y = f2tf(__expf(sv[j4 * 4 + 1] - mx));
                u.z = f2tf(__expf(sv[j4 * 4 + 2] - mx));
                u.w = f2tf(__expf(sv[j4 * 4 + 3] - mx));
                sum += __uint_as_float(u.x) + __uint_as_float(u.y) +
                       __uint_as_float(u.z) + __uint_as_float(u.w);
                *(uint4*)&Ssu[tid * 68 + j4 * 4] = u;
            }
            rowm[tid] = mx;
            rowl[tid] = rowl[tid] * alpha + sum;
            rowa[tid] = alpha;
        }
        __syncthreads();

        // ---- O = O*alpha + P V ----
        {
#pragma unroll
            for (int mt = 0; mt < 4; mt++) {
                float a0 = rowa[wm + mt * 16 + r];
                float a8 = rowa[wm + mt * 16 + r + 8];
#pragma unroll
                for (int nt = 0; nt < 4; nt++) {
                    oacc[mt][nt][0] *= a0; oacc[mt][nt][1] *= a0;
                    oacc[mt][nt][2] *= a8; oacc[mt][nt][3] *= a8;
                }
            }
#pragma unroll
            for (int ks = 0; ks < 8; ks++) {
                int k8 = ks * 8;
                unsigned ua[4][4], ub[4][2];
#pragma unroll
                for (int mt = 0; mt < 4; mt++) {
                    int rr = wm + mt * 16 + r;
                    ua[mt][0] = Ssu[rr * 68 + k8 + c];
                    ua[mt][1] = Ssu[(rr + 8) * 68 + k8 + c];
                    ua[mt][2] = Ssu[rr * 68 + k8 + c + 4];
                    ua[mt][3] = Ssu[(rr + 8) * 68 + k8 + c + 4];
                }
#pragma unroll
                for (int nt = 0; nt < 4; nt++) {
                    int dv = wn + nt * 8 + g;
                    ub[nt][0] = Vs[dv * 68 + k8 + c];
                    ub[nt][1] = Vs[dv * 68 + k8 + c + 4];
                }
#pragma unroll
                for (int mt = 0; mt < 4; mt++)
#pragma unroll
                    for (int nt = 0; nt < 4; nt++)
                        mma_tf32(oacc[mt][nt], ua[mt], ub[nt]);
            }
        }
    }

    // final normalize + write [B,S,H*64]
#pragma unroll
    for (int mt = 0; mt < 4; mt++) {
        float l0 = 1.f / rowl[wm + mt * 16 + r];
        float l8 = 1.f / rowl[wm + mt * 16 + r + 8];
        int rowg = qbase + wm + mt * 16 + r;
#pragma unroll
        for (int nt = 0; nt < 4; nt++) {
            int cc = h * 64 + wn + nt * 8 + 2 * c;
            *(float2*)&O[(size_t)(b * 2048 + rowg) * 1024 + cc] =
                make_float2(oacc[mt][nt][0] * l0, oacc[mt][nt][1] * l0);
            *(float2*)&O[(size_t)(b * 2048 + rowg + 8) * 1024 + cc] =
                make_float2(oacc[mt][nt][2] * l8, oacc[mt][nt][3] * l8);
        }
    }
}

// ---------------------------------------------------------------------------
// residual + LayerNorm
// ---------------------------------------------------------------------------
__global__ void __launch_bounds__(256) ln_kernel(
    const float* __restrict__ Y, const float* __restrict__ R,
    const float* __restrict__ g, const float* __restrict__ bt,
    float* __restrict__ out)
{
    __shared__ float red[2][8];
    int row = blockIdx.x;
    int tid = threadIdx.x;
    int lane = tid & 31, wid = tid >> 5;

    float4 y4 = ((const float4*)(Y + (size_t)row * 1024))[tid];
    float4 r4 = ((const float4*)(R + (size_t)row * 1024))[tid];
    float x0 = y4.x + r4.x, x1 = y4.y + r4.y, x2 = y4.z + r4.z, x3 = y4.w + r4.w;

    float sum = x0 + x1 + x2 + x3;
    float sq  = x0 * x0 + x1 * x1 + x2 * x2 + x3 * x3;
#pragma unroll
    for (int off = 16; off > 0; off >>= 1) {
        sum += __shfl_xor_sync(0xffffffff, sum, off);
        sq  += __shfl_xor_sync(0xffffffff, sq,  off);
    }
    if (lane == 0) { red[0][wid] = sum; red[1][wid] = sq; }
    __syncthreads();
    if (tid == 0) {
        float ts = 0.f, tq = 0.f;
#pragma unroll
        for (int w = 0; w < 8; w++) { ts += red[0][w]; tq += red[1][w]; }
        red[0][0] = ts; red[1][0] = tq;
    }
    __syncthreads();
    float mu  = red[0][0] * (1.f / 1024.f);
    float var = red[1][0] * (1.f / 1024.f) - mu * mu;
    float rstd = rsqrtf(var + 1e-6f);

    float4 g4 = ((const float4*)g)[tid];
    float4 b4 = ((const float4*)bt)[tid];
    float4 o;
    o.x = (x0 - mu) * rstd * g4.x + b4.x;
    o.y = (x1 - mu) * rstd * g4.y + b4.y;
    o.z = (x2 - mu) * rstd * g4.z + b4.z;
    o.w = (x3 - mu) * rstd * g4.w + b4.w;
    ((float4*)(out + (size_t)row * 1024))[tid] = o;
}

// ---------------------------------------------------------------------------
extern "C" void kernel_launch(void* const* d_in, const int* in_sizes, int n_in,
                              void* d_out, int out_size)
{
    const float* query = (const float*)d_in[0];
    const float* key   = (const float*)d_in[1];
    const float* value = (const float*)d_in[2];
    const int*   mask  = (const int*)d_in[3];
    const float* w_qs  = (const float*)d_in[4];
    const float* w_ks  = (const float*)d_in[5];
    const float* w_vs  = (const float*)d_in[6];
    const float* w_out = (const float*)d_in[7];
    const float* ln_g  = (const float*)d_in[8];
    const float* ln_b  = (const float*)d_in[9];
    float* out = (float*)d_out;

    float *q, *k, *v, *attn, *y;
    cudaGetSymbolAddress((void**)&q,    g_q);
    cudaGetSymbolAddress((void**)&k,    g_k);
    cudaGetSymbolAddress((void**)&v,    g_v);
    cudaGetSymbolAddress((void**)&attn, g_attn);
    cudaGetSymbolAddress((void**)&y,    g_y);

    dim3 gg(8, 64);   // N/128, M/128 for M=8192, N=1024

    gemm_tc<<<gg, 256>>>(query, w_qs, q, 8192, 1024, 1024, 1);
    gemm_tc<<<gg, 256>>>(key,   w_ks, k, 8192, 1024, 1024, 1);
    gemm_tc<<<gg, 256>>>(value, w_vs, v, 8192, 1024, 1024, 2);

    cudaFuncSetAttribute(attn_tc,
                         cudaFuncAttributeMaxDynamicSharedMemorySize,
                         ATTN_SMEM);
    attn_tc<<<dim3(16, 16, 4), 128, ATTN_SMEM>>>(q, k, v, mask, attn);

    gemm_tc<<<gg, 256>>>(attn, w_out, y, 8192, 1024, 1024, 0);

    ln_kernel<<<8192, 256>>>(y, query, ln_g, ln_b, out);
}

// round 5
// speedup vs baseline: 3.0392x; 1.0589x over previous
#include <cuda_runtime.h>

// ---------------------------------------------------------------------------
// MultiHeadedAttention: B=4, S=2048, D_MODEL=1024, H=16, DK=DV=64
// Round 5: row-owning warps (32x64 warp tile) with register-resident online
//          softmax (no S smem round trip, barriers 4->2 per k-block),
//          warp-private P buffer, GEMM smem ping-pong (1 barrier/iter).
// ---------------------------------------------------------------------------

#define NEGV (-1e9f)
#define MINIT (-1e38f)

__device__ float g_q[4 * 16 * 2048 * 64];
__device__ float g_k[4 * 16 * 2048 * 64];
__device__ float g_v[4 * 16 * 2048 * 64];   // V^T per head: [B,H,64,2048]
__device__ float g_attn[8192 * 1024];
__device__ float g_y[8192 * 1024];

__device__ __forceinline__ unsigned f2tf(float f) {
    unsigned u;
    asm("cvt.rna.tf32.f32 %0, %1;" : "=r"(u) : "f"(f));
    return u;
}

__device__ __forceinline__ void mma_tf32(float c[4], const unsigned a[4],
                                         const unsigned b[2]) {
    asm volatile(
        "mma.sync.aligned.m16n8k8.row.col.f32.tf32.tf32.f32 "
        "{%0,%1,%2,%3}, {%4,%5,%6,%7}, {%8,%9}, {%0,%1,%2,%3};"
        : "+f"(c[0]), "+f"(c[1]), "+f"(c[2]), "+f"(c[3])
        : "r"(a[0]), "r"(a[1]), "r"(a[2]), "r"(a[3]), "r"(b[0]), "r"(b[1]));
}

// ---------------------------------------------------------------------------
// tf32 GEMM, 128x128 tile, k-tile 32, 256 threads (8 warps, warp 64x32),
// 2-stage smem ping-pong (one barrier per k-iter) + register prefetch.
// mode 0: row-major out.  mode 1: [B,H,S,64].  mode 2: V^T [B,H,64,S].
// ---------------------------------------------------------------------------
#define GEMM_SMEM ((2 * (128 * 36) + 2 * (32 * 132)) * 4)

__global__ void __launch_bounds__(256, 2) gemm_tc(
    const float* __restrict__ A, const float* __restrict__ B,
    float* __restrict__ C, int M, int N, int K, int mode)
{
    extern __shared__ unsigned gsm[];
    unsigned* As[2] = {gsm, gsm + 128 * 36};
    unsigned* Bs[2] = {gsm + 2 * 128 * 36, gsm + 2 * 128 * 36 + 32 * 132};

    int tid = threadIdx.x;
    int wid = tid >> 5, lane = tid & 31;
    int r = lane >> 2, c = lane & 3, g = lane >> 2;
    int m0 = blockIdx.y * 128, n0 = blockIdx.x * 128;
    int wm = (wid & 1) * 64, wn = (wid >> 1) * 32;

    int arow[4], acol[4], brow[4], bcol[4];
#pragma unroll
    for (int i = 0; i < 4; i++) {
        int lin = tid + i * 256;
        arow[i] = lin >> 3;  acol[i] = (lin & 7) << 2;    // A 128x32
        brow[i] = lin >> 5;  bcol[i] = (lin & 31) << 2;   // B 32x128
    }

    float acc[4][4][4];
#pragma unroll
    for (int mt = 0; mt < 4; mt++)
#pragma unroll
        for (int nt = 0; nt < 4; nt++)
#pragma unroll
            for (int i = 0; i < 4; i++) acc[mt][nt][i] = 0.f;

    float4 pa[4], pb[4];
#pragma unroll
    for (int i = 0; i < 4; i++) {
        pa[i] = *(const float4*)&A[(size_t)(m0 + arow[i]) * K + acol[i]];
        pb[i] = *(const float4*)&B[(size_t)brow[i] * N + n0 + bcol[i]];
    }
#pragma unroll
    for (int i = 0; i < 4; i++) {
        uint4 ua = {f2tf(pa[i].x), f2tf(pa[i].y), f2tf(pa[i].z), f2tf(pa[i].w)};
        *(uint4*)&As[0][arow[i] * 36 + acol[i]] = ua;
        uint4 ub = {f2tf(pb[i].x), f2tf(pb[i].y), f2tf(pb[i].z), f2tf(pb[i].w)};
        *(uint4*)&Bs[0][brow[i] * 132 + bcol[i]] = ub;
    }
    __syncthreads();

    int stage = 0;
    for (int k0 = 0; k0 < K; k0 += 32) {
        bool more = (k0 + 32) < K;
        if (more) {
#pragma unroll
            for (int i = 0; i < 4; i++) {
                pa[i] = *(const float4*)&A[(size_t)(m0 + arow[i]) * K + k0 + 32 + acol[i]];
                pb[i] = *(const float4*)&B[(size_t)(k0 + 32 + brow[i]) * N + n0 + bcol[i]];
            }
        }
        const unsigned* Asx = As[stage];
        const unsigned* Bsx = Bs[stage];
#pragma unroll
        for (int ks = 0; ks < 4; ks++) {
            int k8 = ks * 8;
            unsigned ua[4][4], ub[4][2];
#pragma unroll
            for (int mt = 0; mt < 4; mt++) {
                int rr = wm + mt * 16 + r;
                ua[mt][0] = Asx[rr * 36 + k8 + c];
                ua[mt][1] = Asx[(rr + 8) * 36 + k8 + c];
                ua[mt][2] = Asx[rr * 36 + k8 + c + 4];
                ua[mt][3] = Asx[(rr + 8) * 36 + k8 + c + 4];
            }
#pragma unroll
            for (int nt = 0; nt < 4; nt++) {
                int cn = wn + nt * 8 + g;
                ub[nt][0] = Bsx[(k8 + c) * 132 + cn];
                ub[nt][1] = Bsx[(k8 + c + 4) * 132 + cn];
            }
#pragma unroll
            for (int mt = 0; mt < 4; mt++)
#pragma unroll
                for (int nt = 0; nt < 4; nt++)
                    mma_tf32(acc[mt][nt], ua[mt], ub[nt]);
        }
        if (more) {
            int ns = stage ^ 1;
#pragma unroll
            for (int i = 0; i < 4; i++) {
                uint4 ua = {f2tf(pa[i].x), f2tf(pa[i].y), f2tf(pa[i].z), f2tf(pa[i].w)};
                *(uint4*)&As[ns][arow[i] * 36 + acol[i]] = ua;
                uint4 ub = {f2tf(pb[i].x), f2tf(pb[i].y), f2tf(pb[i].z), f2tf(pb[i].w)};
                *(uint4*)&Bs[ns][brow[i] * 132 + bcol[i]] = ub;
            }
            __syncthreads();
            stage = ns;
        }
    }

#pragma unroll
    for (int mt = 0; mt < 4; mt++) {
#pragma unroll
        for (int nt = 0; nt < 4; nt++) {
            int rr = m0 + wm + mt * 16 + r;
            int cc = n0 + wn + nt * 8 + 2 * c;
            float* a4 = acc[mt][nt];
            if (mode == 0) {
                *(float2*)&C[(size_t)rr * N + cc] = make_float2(a4[0], a4[1]);
                *(float2*)&C[(size_t)(rr + 8) * N + cc] = make_float2(a4[2], a4[3]);
            } else if (mode == 1) {
                int b = rr >> 11, s = rr & 2047;
                int h = cc >> 6, d = cc & 63;
                size_t idx = (((size_t)(b * 16 + h) * 2048 + s) << 6) + d;
                *(float2*)&C[idx] = make_float2(a4[0], a4[1]);
                int b2 = (rr + 8) >> 11, s2 = (rr + 8) & 2047;
                size_t idx2 = (((size_t)(b2 * 16 + h) * 2048 + s2) << 6) + d;
                *(float2*)&C[idx2] = make_float2(a4[2], a4[3]);
            } else {  // V^T [B,H,64,2048]
                int b = rr >> 11, s = rr & 2047;
                int h = cc >> 6, d = cc & 63;
                size_t base = ((size_t)(b * 16 + h) * 64 + d) * 2048;
                C[base + s] = a4[0];
                C[base + 2048 + s] = a4[1];
                int b2 = (rr + 8) >> 11, s2 = (rr + 8) & 2047;
                size_t base2 = ((size_t)(b2 * 16 + h) * 64 + d) * 2048;
                C[base2 + s2] = a4[2];
                C[base2 + 2048 + s2] = a4[3];
            }
        }
    }
}

// ---------------------------------------------------------------------------
// Flash attention, register-resident softmax.
// grid = (S/128, H, B), 128 threads (4 warps). Warp owns 32 rows x ALL 64
// cols (wm = wid*32) -> full softmax rows inside one warp: mask on
// fragments, quad-shfl row reductions, P in warp-private smem (no barrier).
// SMEM: Qs[128*68] Ks[64*68] Vs[64*68] Ps[128*68].
// ---------------------------------------------------------------------------
#define ATTN_SMEM ((128 * 68 + 64 * 68 + 64 * 68 + 128 * 68) * 4)

__global__ void __launch_bounds__(128, 2) attn_tc(
    const float* __restrict__ Q, const float* __restrict__ Kg,
    const float* __restrict__ Vt, const int* __restrict__ mask,
    float* __restrict__ O)
{
    extern __shared__ unsigned smu[];
    unsigned* Qs = smu;                    // 128 x 68
    unsigned* Ks = Qs + 128 * 68;          // 64 x 68
    unsigned* Vs = Ks + 64 * 68;           // 64 x 68 (V^T: [dv][kpos])
    unsigned* Ps = Vs + 64 * 68;           // 128 x 68, warp-private rows

    int tid = threadIdx.x;
    int wid = tid >> 5, lane = tid & 31;
    int r = lane >> 2, c = lane & 3;
    int qt = blockIdx.x, h = blockIdx.y, b = blockIdx.z;
    int qbase = qt * 128;
    int wm = wid * 32;

    const float* qp  = Q  + (((size_t)(b * 16 + h) * 2048 + qbase) << 6);
    const float* kp0 = Kg + (((size_t)(b * 16 + h) * 2048) << 6);
    const float* vt0 = Vt + ((size_t)(b * 16 + h) * 64) * 2048;

    // mask row pointers for this thread's 4 row slots [mt][half]
    const int* mrow[2][2];
#pragma unroll
    for (int mt = 0; mt < 2; mt++)
#pragma unroll
        for (int hf = 0; hf < 2; hf++)
            mrow[mt][hf] = mask +
                ((size_t)(b * 2048 + qbase + wm + mt * 16 + r + hf * 8)) * 2048 +
                2 * c;

    // stage Q tile (128x64 -> tf32)
#pragma unroll
    for (int i = 0; i < 16; i++) {
        int lin = tid + i * 128;
        int row = lin >> 4, c4 = (lin & 15) << 2;
        float4 q4 = *(const float4*)&qp[row * 64 + c4];
        uint4 u = {f2tf(q4.x), f2tf(q4.y), f2tf(q4.z), f2tf(q4.w)};
        *(uint4*)&Qs[row * 68 + c4] = u;
    }

    float m_[2][2], l_[2][2];
#pragma unroll
    for (int mt = 0; mt < 2; mt++)
#pragma unroll
        for (int hf = 0; hf < 2; hf++) { m_[mt][hf] = MINIT; l_[mt][hf] = 0.f; }

    float oacc[2][8][4];
#pragma unroll
    for (int mt = 0; mt < 2; mt++)
#pragma unroll
        for (int nt = 0; nt < 8; nt++)
#pragma unroll
            for (int i = 0; i < 4; i++) oacc[mt][nt][i] = 0.f;

    for (int kb = 0; kb < 2048; kb += 64) {
        __syncthreads();
        // stage K tile + V^T tile (each 64x64)
#pragma unroll
        for (int i = 0; i < 8; i++) {
            int lin = tid + i * 128;
            int row = lin >> 4, c4 = (lin & 15) << 2;
            float4 k4 = *(const float4*)&kp0[(size_t)(kb + row) * 64 + c4];
            uint4 uk = {f2tf(k4.x), f2tf(k4.y), f2tf(k4.z), f2tf(k4.w)};
            *(uint4*)&Ks[row * 68 + c4] = uk;
            float4 v4 = *(const float4*)&vt0[(size_t)row * 2048 + kb + c4];
            uint4 uv = {f2tf(v4.x), f2tf(v4.y), f2tf(v4.z), f2tf(v4.w)};
            *(uint4*)&Vs[row * 68 + c4] = uv;
        }
        __syncthreads();

        // ---- S = Q K^T (fragments stay in registers) ----
        float sacc[2][8][4];
#pragma unroll
        for (int mt = 0; mt < 2; mt++)
#pragma unroll
            for (int nt = 0; nt < 8; nt++)
#pragma unroll
                for (int i = 0; i < 4; i++) sacc[mt][nt][i] = 0.f;

#pragma unroll
        for (int ks = 0; ks < 8; ks++) {
            int k8 = ks * 8;
            unsigned ua[2][4];
#pragma unroll
            for (int mt = 0; mt < 2; mt++) {
                int rr = wm + mt * 16 + r;
                ua[mt][0] = Qs[rr * 68 + k8 + c];
                ua[mt][1] = Qs[(rr + 8) * 68 + k8 + c];
                ua[mt][2] = Qs[rr * 68 + k8 + c + 4];
                ua[mt][3] = Qs[(rr + 8) * 68 + k8 + c + 4];
            }
#pragma unroll
            for (int nt = 0; nt < 8; nt++) {
                unsigned ub[2] = {Ks[(nt * 8 + r) * 68 + k8 + c],
                                  Ks[(nt * 8 + r) * 68 + k8 + c + 4]};
                mma_tf32(sacc[0][nt], ua[0], ub);
                mma_tf32(sacc[1][nt], ua[1], ub);
            }
        }

        // ---- mask + online softmax in registers ----
#pragma unroll
        for (int mt = 0; mt < 2; mt++) {
            float mx0 = m_[mt][0], mx1 = m_[mt][1];
#pragma unroll
            for (int nt = 0; nt < 8; nt++) {
                int2 mk0 = *(const int2*)(mrow[mt][0] + kb + nt * 8);
                int2 mk1 = *(const int2*)(mrow[mt][1] + kb + nt * 8);
                float s0 = mk0.x ? sacc[mt][nt][0] * 0.125f : NEGV;
                float s1 = mk0.y ? sacc[mt][nt][1] * 0.125f : NEGV;
                float s2 = mk1.x ? sacc[mt][nt][2] * 0.125f : NEGV;
                float s3 = mk1.y ? sacc[mt][nt][3] * 0.125f : NEGV;
                sacc[mt][nt][0] = s0; sacc[mt][nt][1] = s1;
                sacc[mt][nt][2] = s2; sacc[mt][nt][3] = s3;
                mx0 = fmaxf(mx0, fmaxf(s0, s1));
                mx1 = fmaxf(mx1, fmaxf(s2, s3));
            }
            mx0 = fmaxf(mx0, __shfl_xor_sync(0xffffffffu, mx0, 1));
            mx0 = fmaxf(mx0, __shfl_xor_sync(0xffffffffu, mx0, 2));
            mx1 = fmaxf(mx1, __shfl_xor_sync(0xffffffffu, mx1, 1));
            mx1 = fmaxf(mx1, __shfl_xor_sync(0xffffffffu, mx1, 2));

            float al0 = __expf(m_[mt][0] - mx0);
            float al1 = __expf(m_[mt][1] - mx1);
            float sum0 = 0.f, sum1 = 0.f;
            int rr = wm + mt * 16 + r;
#pragma unroll
            for (int nt = 0; nt < 8; nt++) {
                unsigned p0 = f2tf(__expf(sacc[mt][nt][0] - mx0));
                unsigned p1 = f2tf(__expf(sacc[mt][nt][1] - mx0));
                unsigned p2 = f2tf(__expf(sacc[mt][nt][2] - mx1));
                unsigned p3 = f2tf(__expf(sacc[mt][nt][3] - mx1));
                sum0 += __uint_as_float(p0) + __uint_as_float(p1);
                sum1 += __uint_as_float(p2) + __uint_as_float(p3);
                *(uint2*)&Ps[rr * 68 + nt * 8 + 2 * c] = make_uint2(p0, p1);
                *(uint2*)&Ps[(rr + 8) * 68 + nt * 8 + 2 * c] = make_uint2(p2, p3);
            }
            sum0 += __shfl_xor_sync(0xffffffffu, sum0, 1);
            sum0 += __shfl_xor_sync(0xffffffffu, sum0, 2);
            sum1 += __shfl_xor_sync(0xffffffffu, sum1, 1);
            sum1 += __shfl_xor_sync(0xffffffffu, sum1, 2);

            m_[mt][0] = mx0; m_[mt][1] = mx1;
            l_[mt][0] = l_[mt][0] * al0 + sum0;
            l_[mt][1] = l_[mt][1] * al1 + sum1;
#pragma unroll
            for (int nt = 0; nt < 8; nt++) {
                oacc[mt][nt][0] *= al0; oacc[mt][nt][1] *= al0;
                oacc[mt][nt][2] *= al1; oacc[mt][nt][3] *= al1;
            }
        }
        __syncwarp();   // Ps rows are warp-private: no block barrier needed

        // ---- O += P V ----
#pragma unroll
        for (int ks = 0; ks < 8; ks++) {
            int k8 = ks * 8;
            unsigned ua[2][4];
#pragma unroll
            for (int mt = 0; mt < 2; mt++) {
                int rr = wm + mt * 16 + r;
                ua[mt][0] = Ps[rr * 68 + k8 + c];
                ua[mt][1] = Ps[(rr + 8) * 68 + k8 + c];
                ua[mt][2] = Ps[rr * 68 + k8 + c + 4];
                ua[mt][3] = Ps[(rr + 8) * 68 + k8 + c + 4];
            }
#pragma unroll
            for (int nt = 0; nt < 8; nt++) {
                unsigned ub[2] = {Vs[(nt * 8 + r) * 68 + k8 + c],
                                  Vs[(nt * 8 + r) * 68 + k8 + c + 4]};
                mma_tf32(oacc[0][nt], ua[0], ub);
                mma_tf32(oacc[1][nt], ua[1], ub);
            }
        }
    }

    // final normalize + write [B,S,H*64]
#pragma unroll
    for (int mt = 0; mt < 2; mt++) {
        float l0 = 1.f / l_[mt][0];
        float l1 = 1.f / l_[mt][1];
        int rowg = qbase + wm + mt * 16 + r;
#pragma unroll
        for (int nt = 0; nt < 8; nt++) {
            int cc = h * 64 + nt * 8 + 2 * c;
            *(float2*)&O[(size_t)(b * 2048 + rowg) * 1024 + cc] =
                make_float2(oacc[mt][nt][0] * l0, oacc[mt][nt][1] * l0);
            *(float2*)&O[(size_t)(b * 2048 + rowg + 8) * 1024 + cc] =
                make_float2(oacc[mt][nt][2] * l1, oacc[mt][nt][3] * l1);
        }
    }
}

// ---------------------------------------------------------------------------
// residual + LayerNorm
// ---------------------------------------------------------------------------
__global__ void __launch_bounds__(256) ln_kernel(
    const float* __restrict__ Y, const float* __restrict__ R,
    const float* __restrict__ g, const float* __restrict__ bt,
    float* __restrict__ out)
{
    __shared__ float red[2][8];
    int row = blockIdx.x;
    int tid = threadIdx.x;
    int lane = tid & 31, wid = tid >> 5;

    float4 y4 = ((const float4*)(Y + (size_t)row * 1024))[tid];
    float4 r4 = ((const float4*)(R + (size_t)row * 1024))[tid];
    float x0 = y4.x + r4.x, x1 = y4.y + r4.y, x2 = y4.z + r4.z, x3 = y4.w + r4.w;

    float sum = x0 + x1 + x2 + x3;
    float sq  = x0 * x0 + x1 * x1 + x2 * x2 + x3 * x3;
#pragma unroll
    for (int off = 16; off > 0; off >>= 1) {
        sum += __shfl_xor_sync(0xffffffff, sum, off);
        sq  += __shfl_xor_sync(0xffffffff, sq,  off);
    }
    if (lane == 0) { red[0][wid] = sum; red[1][wid] = sq; }
    __syncthreads();
    if (tid == 0) {
        float ts = 0.f, tq = 0.f;
#pragma unroll
        for (int w = 0; w < 8; w++) { ts += red[0][w]; tq += red[1][w]; }
        red[0][0] = ts; red[1][0] = tq;
    }
    __syncthreads();
    float mu  = red[0][0] * (1.f / 1024.f);
    float var = red[1][0] * (1.f / 1024.f) - mu * mu;
    float rstd = rsqrtf(var + 1e-6f);

    float4 g4 = ((const float4*)g)[tid];
    float4 b4 = ((const float4*)bt)[tid];
    float4 o;
    o.x = (x0 - mu) * rstd * g4.x + b4.x;
    o.y = (x1 - mu) * rstd * g4.y + b4.y;
    o.z = (x2 - mu) * rstd * g4.z + b4.z;
    o.w = (x3 - mu) * rstd * g4.w + b4.w;
    ((float4*)(out + (size_t)row * 1024))[tid] = o;
}

// ---------------------------------------------------------------------------
extern "C" void kernel_launch(void* const* d_in, const int* in_sizes, int n_in,
                              void* d_out, int out_size)
{
    const float* query = (const float*)d_in[0];
    const float* key   = (const float*)d_in[1];
    const float* value = (const float*)d_in[2];
    const int*   mask  = (const int*)d_in[3];
    const float* w_qs  = (const float*)d_in[4];
    const float* w_ks  = (const float*)d_in[5];
    const float* w_vs  = (const float*)d_in[6];
    const float* w_out = (const float*)d_in[7];
    const float* ln_g  = (const float*)d_in[8];
    const float* ln_b  = (const float*)d_in[9];
    float* out = (float*)d_out;

    float *q, *k, *v, *attn, *y;
    cudaGetSymbolAddress((void**)&q,    g_q);
    cudaGetSymbolAddress((void**)&k,    g_k);
    cudaGetSymbolAddress((void**)&v,    g_v);
    cudaGetSymbolAddress((void**)&attn, g_attn);
    cudaGetSymbolAddress((void**)&y,    g_y);

    cudaFuncSetAttribute(gemm_tc,
                         cudaFuncAttributeMaxDynamicSharedMemorySize,
                         GEMM_SMEM);
    cudaFuncSetAttribute(attn_tc,
                         cudaFuncAttributeMaxDynamicSharedMemorySize,
                         ATTN_SMEM);

    dim3 gg(8, 64);   // N/128, M/128 for M=8192, N=1024

    gemm_tc<<<gg, 256, GEMM_SMEM>>>(query, w_qs, q, 8192, 1024, 1024, 1);
    gemm_tc<<<gg, 256, GEMM_SMEM>>>(key,   w_ks, k, 8192, 1024, 1024, 1);
    gemm_tc<<<gg, 256, GEMM_SMEM>>>(value, w_vs, v, 8192, 1024, 1024, 2);

    attn_tc<<<dim3(16, 16, 4), 128, ATTN_SMEM>>>(q, k, v, mask, attn);

    gemm_tc<<<gg, 256, GEMM_SMEM>>>(attn, w_out, y, 8192, 1024, 1024, 0);

    ln_kernel<<<8192, 256>>>(y, query, ln_g, ln_b, out);
}

// round 6
// speedup vs baseline: 3.7350x; 1.2289x over previous
#include <cuda_runtime.h>
#include <cuda_bf16.h>

// ---------------------------------------------------------------------------
// MultiHeadedAttention: B=4, S=2048, D_MODEL=1024, H=16, DK=DV=64
// Round 6: bf16 attention (ldmatrix + mma.m16n8k16, log2-domain softmax),
//          projections emit bf16; GEMM reverted to R4 shape (regression fix).
// ---------------------------------------------------------------------------

#define NEGV (-1e9f)
#define MINIT (-1e38f)

__device__ __nv_bfloat16 g_q[4 * 16 * 2048 * 64];
__device__ __nv_bfloat16 g_k[4 * 16 * 2048 * 64];
__device__ __nv_bfloat16 g_v[4 * 16 * 2048 * 64];   // V^T per head [B,H,64,2048]
__device__ float g_attn[8192 * 1024];
__device__ float g_y[8192 * 1024];

__device__ __forceinline__ unsigned f2tf(float f) {
    unsigned u;
    asm("cvt.rna.tf32.f32 %0, %1;" : "=r"(u) : "f"(f));
    return u;
}

__device__ __forceinline__ void mma_tf32(float c[4], const unsigned a[4],
                                         const unsigned b[2]) {
    asm volatile(
        "mma.sync.aligned.m16n8k8.row.col.f32.tf32.tf32.f32 "
        "{%0,%1,%2,%3}, {%4,%5,%6,%7}, {%8,%9}, {%0,%1,%2,%3};"
        : "+f"(c[0]), "+f"(c[1]), "+f"(c[2]), "+f"(c[3])
        : "r"(a[0]), "r"(a[1]), "r"(a[2]), "r"(a[3]), "r"(b[0]), "r"(b[1]));
}

__device__ __forceinline__ void mma_bf16(float c[4], const unsigned a[4],
                                         const unsigned b[2]) {
    asm volatile(
        "mma.sync.aligned.m16n8k16.row.col.f32.bf16.bf16.f32 "
        "{%0,%1,%2,%3}, {%4,%5,%6,%7}, {%8,%9}, {%0,%1,%2,%3};"
        : "+f"(c[0]), "+f"(c[1]), "+f"(c[2]), "+f"(c[3])
        : "r"(a[0]), "r"(a[1]), "r"(a[2]), "r"(a[3]), "r"(b[0]), "r"(b[1]));
}

__device__ __forceinline__ void ldsm4(unsigned& r0, unsigned& r1,
                                      unsigned& r2, unsigned& r3,
                                      const void* p) {
    unsigned a = (unsigned)__cvta_generic_to_shared(p);
    asm volatile(
        "ldmatrix.sync.aligned.m8n8.x4.shared.b16 {%0,%1,%2,%3}, [%4];"
        : "=r"(r0), "=r"(r1), "=r"(r2), "=r"(r3) : "r"(a));
}

__device__ __forceinline__ float ex2(float x) {
    float y;
    asm("ex2.approx.f32 %0, %1;" : "=f"(y) : "f"(x));
    return y;
}

__device__ __forceinline__ unsigned pack_bf16(float lo, float hi) {
    unsigned u;
    asm("cvt.rn.bf16x2.f32 %0, %1, %2;" : "=r"(u) : "f"(hi), "f"(lo));
    return u;
}

// ---------------------------------------------------------------------------
// tf32 GEMM (R4 shape: static smem, register prefetch, 2 barriers/iter).
// 128x128 tile, k-tile 32, 256 threads (8 warps, warp 64x32).
// mode 0: fp32 row-major. mode 1: bf16 [B,H,S,64]. mode 2: bf16 V^T [B,H,64,S].
// ---------------------------------------------------------------------------
__global__ void __launch_bounds__(256) gemm_tc(
    const float* __restrict__ A, const float* __restrict__ B,
    void* __restrict__ Cv, int M, int N, int K, int mode)
{
    __shared__ unsigned As[128 * 36];
    __shared__ unsigned Bs[32 * 132];

    int tid = threadIdx.x;
    int wid = tid >> 5, lane = tid & 31;
    int r = lane >> 2, c = lane & 3, g = lane >> 2;
    int m0 = blockIdx.y * 128, n0 = blockIdx.x * 128;
    int wm = (wid & 1) * 64, wn = (wid >> 1) * 32;

    int arow[4], acol[4], brow[4], bcol[4];
#pragma unroll
    for (int i = 0; i < 4; i++) {
        int lin = tid + i * 256;
        arow[i] = lin >> 3;  acol[i] = (lin & 7) << 2;
        brow[i] = lin >> 5;  bcol[i] = (lin & 31) << 2;
    }

    float acc[4][4][4];
#pragma unroll
    for (int mt = 0; mt < 4; mt++)
#pragma unroll
        for (int nt = 0; nt < 4; nt++)
#pragma unroll
            for (int i = 0; i < 4; i++) acc[mt][nt][i] = 0.f;

    float4 pa[4], pb[4];
#pragma unroll
    for (int i = 0; i < 4; i++) {
        pa[i] = *(const float4*)&A[(size_t)(m0 + arow[i]) * K + acol[i]];
        pb[i] = *(const float4*)&B[(size_t)brow[i] * N + n0 + bcol[i]];
    }

    for (int k0 = 0; k0 < K; k0 += 32) {
        __syncthreads();
#pragma unroll
        for (int i = 0; i < 4; i++) {
            uint4 ua = {f2tf(pa[i].x), f2tf(pa[i].y), f2tf(pa[i].z), f2tf(pa[i].w)};
            *(uint4*)&As[arow[i] * 36 + acol[i]] = ua;
            uint4 ub = {f2tf(pb[i].x), f2tf(pb[i].y), f2tf(pb[i].z), f2tf(pb[i].w)};
            *(uint4*)&Bs[brow[i] * 132 + bcol[i]] = ub;
        }
        if (k0 + 32 < K) {
#pragma unroll
            for (int i = 0; i < 4; i++) {
                pa[i] = *(const float4*)&A[(size_t)(m0 + arow[i]) * K + k0 + 32 + acol[i]];
                pb[i] = *(const float4*)&B[(size_t)(k0 + 32 + brow[i]) * N + n0 + bcol[i]];
            }
        }
        __syncthreads();

#pragma unroll
        for (int ks = 0; ks < 4; ks++) {
            int k8 = ks * 8;
            unsigned ua[4][4], ub[4][2];
#pragma unroll
            for (int mt = 0; mt < 4; mt++) {
                int rr = wm + mt * 16 + r;
                ua[mt][0] = As[rr * 36 + k8 + c];
                ua[mt][1] = As[(rr + 8) * 36 + k8 + c];
                ua[mt][2] = As[rr * 36 + k8 + c + 4];
                ua[mt][3] = As[(rr + 8) * 36 + k8 + c + 4];
            }
#pragma unroll
            for (int nt = 0; nt < 4; nt++) {
                int cn = wn + nt * 8 + g;
                ub[nt][0] = Bs[(k8 + c) * 132 + cn];
                ub[nt][1] = Bs[(k8 + c + 4) * 132 + cn];
            }
#pragma unroll
            for (int mt = 0; mt < 4; mt++)
#pragma unroll
                for (int nt = 0; nt < 4; nt++)
                    mma_tf32(acc[mt][nt], ua[mt], ub[nt]);
        }
    }

#pragma unroll
    for (int mt = 0; mt < 4; mt++) {
#pragma unroll
        for (int nt = 0; nt < 4; nt++) {
            int rr = m0 + wm + mt * 16 + r;
            int cc = n0 + wn + nt * 8 + 2 * c;
            float* a4 = acc[mt][nt];
            if (mode == 0) {
                float* C = (float*)Cv;
                *(float2*)&C[(size_t)rr * N + cc] = make_float2(a4[0], a4[1]);
                *(float2*)&C[(size_t)(rr + 8) * N + cc] = make_float2(a4[2], a4[3]);
            } else if (mode == 1) {
                __nv_bfloat16* C = (__nv_bfloat16*)Cv;
                int b = rr >> 11, s = rr & 2047;
                int h = cc >> 6, d = cc & 63;
                size_t idx = (((size_t)(b * 16 + h) * 2048 + s) << 6) + d;
                *(__nv_bfloat162*)&C[idx] = __floats2bfloat162_rn(a4[0], a4[1]);
                int b2 = (rr + 8) >> 11, s2 = (rr + 8) & 2047;
                size_t idx2 = (((size_t)(b2 * 16 + h) * 2048 + s2) << 6) + d;
                *(__nv_bfloat162*)&C[idx2] = __floats2bfloat162_rn(a4[2], a4[3]);
            } else {  // mode 2: bf16 V^T [B,H,64,2048]
                __nv_bfloat16* C = (__nv_bfloat16*)Cv;
                int b = rr >> 11, s = rr & 2047;
                int h = cc >> 6, d = cc & 63;
                size_t base = ((size_t)(b * 16 + h) * 64 + d) * 2048;
                C[base + s] = __float2bfloat16_rn(a4[0]);
                C[base + 2048 + s] = __float2bfloat16_rn(a4[1]);
                int b2 = (rr + 8) >> 11, s2 = (rr + 8) & 2047;
                size_t base2 = ((size_t)(b2 * 16 + h) * 64 + d) * 2048;
                C[base2 + s2] = __float2bfloat16_rn(a4[2]);
                C[base2 + 2048 + s2] = __float2bfloat16_rn(a4[3]);
            }
        }
    }
}

// ---------------------------------------------------------------------------
// Flash attention, bf16 mma.m16n8k16 + ldmatrix. grid (S/128, H, B), 128 thr.
// Warp owns 32 rows x 64 cols; register softmax in log2 domain.
// SMEM bf16 stride 72: Qs[128] Ks[64] Vs[64] Ps[128]  (54 KB)
// ---------------------------------------------------------------------------
#define SQ 72
#define ATTN_SMEM ((128 + 64 + 64 + 128) * SQ * 2)

__global__ void __launch_bounds__(128, 2) attn_tc(
    const __nv_bfloat16* __restrict__ Q, const __nv_bfloat16* __restrict__ Kg,
    const __nv_bfloat16* __restrict__ Vt, const int* __restrict__ mask,
    float* __restrict__ O)
{
    extern __shared__ __align__(16) __nv_bfloat16 smb[];
    __nv_bfloat16* Qs = smb;                 // 128 x 72
    __nv_bfloat16* Ks = Qs + 128 * SQ;       // 64 x 72  [key][d]
    __nv_bfloat16* Vs = Ks + 64 * SQ;        // 64 x 72  [dv][key]
    __nv_bfloat16* Ps = Vs + 64 * SQ;        // 128 x 72

    int tid = threadIdx.x;
    int wid = tid >> 5, lane = tid & 31;
    int r = lane >> 2, c = lane & 3;
    int qt = blockIdx.x, h = blockIdx.y, b = blockIdx.z;
    int qbase = qt * 128;
    int wm = wid * 32;

    const float SC = 0.125f * 1.44269504088896f;   // scale * log2(e)

    const __nv_bfloat16* qp  = Q  + (((size_t)(b * 16 + h) * 2048 + qbase) << 6);
    const __nv_bfloat16* kp0 = Kg + (((size_t)(b * 16 + h) * 2048) << 6);
    const __nv_bfloat16* vt0 = Vt + ((size_t)(b * 16 + h) * 64) * 2048;

    const int* mrow[2][2];
#pragma unroll
    for (int mt = 0; mt < 2; mt++)
#pragma unroll
        for (int hf = 0; hf < 2; hf++)
            mrow[mt][hf] = mask +
                ((size_t)(b * 2048 + qbase + wm + mt * 16 + r + hf * 8)) * 2048 +
                2 * c;

    // stage Q tile (128x64 bf16, raw copy)
#pragma unroll
    for (int i = 0; i < 8; i++) {
        int lin = tid + i * 128;
        int row = lin >> 3, ch = (lin & 7) << 3;
        *(uint4*)&Qs[row * SQ + ch] = *(const uint4*)&qp[row * 64 + ch];
    }

    // ldmatrix lane addressing
    int la_row = lane & 15;                  // + tile row base
    int la_col = (lane >> 4) << 3;           // 0 or 8 within k16
    int lb_row = ((lane >> 4) << 3) + (lane & 7);
    int lb_col = ((lane >> 3) & 1) << 3;

    float m_[2][2], l_[2][2];
#pragma unroll
    for (int mt = 0; mt < 2; mt++)
#pragma unroll
        for (int hf = 0; hf < 2; hf++) { m_[mt][hf] = MINIT; l_[mt][hf] = 0.f; }

    float oacc[2][8][4];
#pragma unroll
    for (int mt = 0; mt < 2; mt++)
#pragma unroll
        for (int nt = 0; nt < 8; nt++)
#pragma unroll
            for (int i = 0; i < 4; i++) oacc[mt][nt][i] = 0.f;

    for (int kb = 0; kb < 2048; kb += 64) {
        __syncthreads();
        // stage K [key][d] and V^T [dv][key] tiles (64x64 bf16 each)
#pragma unroll
        for (int i = 0; i < 4; i++) {
            int lin = tid + i * 128;
            int row = lin >> 3, ch = (lin & 7) << 3;
            *(uint4*)&Ks[row * SQ + ch] =
                *(const uint4*)&kp0[(size_t)(kb + row) * 64 + ch];
            *(uint4*)&Vs[row * SQ + ch] =
                *(const uint4*)&vt0[(size_t)row * 2048 + kb + ch];
        }
        __syncthreads();

        // ---- S = Q K^T ----
        float sacc[2][8][4];
#pragma unroll
        for (int mt = 0; mt < 2; mt++)
#pragma unroll
            for (int nt = 0; nt < 8; nt++)
#pragma unroll
                for (int i = 0; i < 4; i++) sacc[mt][nt][i] = 0.f;

#pragma unroll
        for (int ks = 0; ks < 4; ks++) {
            int k16 = ks * 16;
            unsigned ua[2][4], ubs[8][2];
#pragma unroll
            for (int mt = 0; mt < 2; mt++)
                ldsm4(ua[mt][0], ua[mt][1], ua[mt][2], ua[mt][3],
                      &Qs[(wm + mt * 16 + la_row) * SQ + k16 + la_col]);
#pragma unroll
            for (int nt2 = 0; nt2 < 4; nt2++) {
                unsigned r0, r1, r2, r3;
                ldsm4(r0, r1, r2, r3,
                      &Ks[(nt2 * 16 + lb_row) * SQ + k16 + lb_col]);
                ubs[nt2 * 2][0] = r0;  ubs[nt2 * 2][1] = r1;
                ubs[nt2 * 2 + 1][0] = r2;  ubs[nt2 * 2 + 1][1] = r3;
            }
#pragma unroll
            for (int mt = 0; mt < 2; mt++)
#pragma unroll
                for (int nt = 0; nt < 8; nt++)
                    mma_bf16(sacc[mt][nt], ua[mt], ubs[nt]);
        }

        // ---- mask + online softmax (log2 domain) ----
#pragma unroll
        for (int mt = 0; mt < 2; mt++) {
            float mx0 = m_[mt][0], mx1 = m_[mt][1];
#pragma unroll
            for (int nt = 0; nt < 8; nt++) {
                int2 mk0 = *(const int2*)(mrow[mt][0] + kb + nt * 8);
                int2 mk1 = *(const int2*)(mrow[mt][1] + kb + nt * 8);
                float s0 = mk0.x ? sacc[mt][nt][0] * SC : NEGV;
                float s1 = mk0.y ? sacc[mt][nt][1] * SC : NEGV;
                float s2 = mk1.x ? sacc[mt][nt][2] * SC : NEGV;
                float s3 = mk1.y ? sacc[mt][nt][3] * SC : NEGV;
                sacc[mt][nt][0] = s0; sacc[mt][nt][1] = s1;
                sacc[mt][nt][2] = s2; sacc[mt][nt][3] = s3;
                mx0 = fmaxf(mx0, fmaxf(s0, s1));
                mx1 = fmaxf(mx1, fmaxf(s2, s3));
            }
            mx0 = fmaxf(mx0, __shfl_xor_sync(0xffffffffu, mx0, 1));
            mx0 = fmaxf(mx0, __shfl_xor_sync(0xffffffffu, mx0, 2));
            mx1 = fmaxf(mx1, __shfl_xor_sync(0xffffffffu, mx1, 1));
            mx1 = fmaxf(mx1, __shfl_xor_sync(0xffffffffu, mx1, 2));

            float al0 = ex2(m_[mt][0] - mx0);
            float al1 = ex2(m_[mt][1] - mx1);
            float sum0 = 0.f, sum1 = 0.f;
            int rr = wm + mt * 16 + r;
#pragma unroll
            for (int nt = 0; nt < 8; nt++) {
                float p0 = ex2(sacc[mt][nt][0] - mx0);
                float p1 = ex2(sacc[mt][nt][1] - mx0);
                float p2 = ex2(sacc[mt][nt][2] - mx1);
                float p3 = ex2(sacc[mt][nt][3] - mx1);
                sum0 += p0 + p1;
                sum1 += p2 + p3;
                *(unsigned*)&Ps[rr * SQ + nt * 8 + 2 * c] = pack_bf16(p0, p1);
                *(unsigned*)&Ps[(rr + 8) * SQ + nt * 8 + 2 * c] = pack_bf16(p2, p3);
            }
            sum0 += __shfl_xor_sync(0xffffffffu, sum0, 1);
            sum0 += __shfl_xor_sync(0xffffffffu, sum0, 2);
            sum1 += __shfl_xor_sync(0xffffffffu, sum1, 1);
            sum1 += __shfl_xor_sync(0xffffffffu, sum1, 2);

            m_[mt][0] = mx0; m_[mt][1] = mx1;
            l_[mt][0] = l_[mt][0] * al0 + sum0;
            l_[mt][1] = l_[mt][1] * al1 + sum1;
#pragma unroll
            for (int nt = 0; nt < 8; nt++) {
                oacc[mt][nt][0] *= al0; oacc[mt][nt][1] *= al0;
                oacc[mt][nt][2] *= al1; oacc[mt][nt][3] *= al1;
            }
        }
        __syncwarp();   // Ps rows are warp-private

        // ---- O += P V ----
#pragma unroll
        for (int ks = 0; ks < 4; ks++) {
            int k16 = ks * 16;
            unsigned ua[2][4], ubs[8][2];
#pragma unroll
            for (int mt = 0; mt < 2; mt++)
                ldsm4(ua[mt][0], ua[mt][1], ua[mt][2], ua[mt][3],
                      &Ps[(wm + mt * 16 + la_row) * SQ + k16 + la_col]);
#pragma unroll
            for (int nt2 = 0; nt2 < 4; nt2++) {
                unsigned r0, r1, r2, r3;
                ldsm4(r0, r1, r2, r3,
                      &Vs[(nt2 * 16 + lb_row) * SQ + k16 + lb_col]);
                ubs[nt2 * 2][0] = r0;  ubs[nt2 * 2][1] = r1;
                ubs[nt2 * 2 + 1][0] = r2;  ubs[nt2 * 2 + 1][1] = r3;
            }
#pragma unroll
            for (int mt = 0; mt < 2; mt++)
#pragma unroll
                for (int nt = 0; nt < 8; nt++)
                    mma_bf16(oacc[mt][nt], ua[mt], ubs[nt]);
        }
    }

    // final normalize + write [B,S,H*64] fp32
#pragma unroll
    for (int mt = 0; mt < 2; mt++) {
        float l0 = 1.f / l_[mt][0];
        float l1 = 1.f / l_[mt][1];
        int rowg = qbase + wm + mt * 16 + r;
#pragma unroll
        for (int nt = 0; nt < 8; nt++) {
            int cc = h * 64 + nt * 8 + 2 * c;
            *(float2*)&O[(size_t)(b * 2048 + rowg) * 1024 + cc] =
                make_float2(oacc[mt][nt][0] * l0, oacc[mt][nt][1] * l0);
            *(float2*)&O[(size_t)(b * 2048 + rowg + 8) * 1024 + cc] =
                make_float2(oacc[mt][nt][2] * l1, oacc[mt][nt][3] * l1);
        }
    }
}

// ---------------------------------------------------------------------------
// residual + LayerNorm
// ---------------------------------------------------------------------------
__global__ void __launch_bounds__(256) ln_kernel(
    const float* __restrict__ Y, const float* __restrict__ R,
    const float* __restrict__ g, const float* __restrict__ bt,
    float* __restrict__ out)
{
    __shared__ float red[2][8];
    int row = blockIdx.x;
    int tid = threadIdx.x;
    int lane = tid & 31, wid = tid >> 5;

    float4 y4 = ((const float4*)(Y + (size_t)row * 1024))[tid];
    float4 r4 = ((const float4*)(R + (size_t)row * 1024))[tid];
    float x0 = y4.x + r4.x, x1 = y4.y + r4.y, x2 = y4.z + r4.z, x3 = y4.w + r4.w;

    float sum = x0 + x1 + x2 + x3;
    float sq  = x0 * x0 + x1 * x1 + x2 * x2 + x3 * x3;
#pragma unroll
    for (int off = 16; off > 0; off >>= 1) {
        sum += __shfl_xor_sync(0xffffffff, sum, off);
        sq  += __shfl_xor_sync(0xffffffff, sq,  off);
    }
    if (lane == 0) { red[0][wid] = sum; red[1][wid] = sq; }
    __syncthreads();
    if (tid == 0) {
        float ts = 0.f, tq = 0.f;
#pragma unroll
        for (int w = 0; w < 8; w++) { ts += red[0][w]; tq += red[1][w]; }
        red[0][0] = ts; red[1][0] = tq;
    }
    __syncthreads();
    float mu  = red[0][0] * (1.f / 1024.f);
    float var = red[1][0] * (1.f / 1024.f) - mu * mu;
    float rstd = rsqrtf(var + 1e-6f);

    float4 g4 = ((const float4*)g)[tid];
    float4 b4 = ((const float4*)bt)[tid];
    float4 o;
    o.x = (x0 - mu) * rstd * g4.x + b4.x;
    o.y = (x1 - mu) * rstd * g4.y + b4.y;
    o.z = (x2 - mu) * rstd * g4.z + b4.z;
    o.w = (x3 - mu) * rstd * g4.w + b4.w;
    ((float4*)(out + (size_t)row * 1024))[tid] = o;
}

// ---------------------------------------------------------------------------
extern "C" void kernel_launch(void* const* d_in, const int* in_sizes, int n_in,
                              void* d_out, int out_size)
{
    const float* query = (const float*)d_in[0];
    const float* key   = (const float*)d_in[1];
    const float* value = (const float*)d_in[2];
    const int*   mask  = (const int*)d_in[3];
    const float* w_qs  = (const float*)d_in[4];
    const float* w_ks  = (const float*)d_in[5];
    const float* w_vs  = (const float*)d_in[6];
    const float* w_out = (const float*)d_in[7];
    const float* ln_g  = (const float*)d_in[8];
    const float* ln_b  = (const float*)d_in[9];
    float* out = (float*)d_out;

    __nv_bfloat16 *q, *k, *v;
    float *attn, *y;
    cudaGetSymbolAddress((void**)&q,    g_q);
    cudaGetSymbolAddress((void**)&k,    g_k);
    cudaGetSymbolAddress((void**)&v,    g_v);
    cudaGetSymbolAddress((void**)&attn, g_attn);
    cudaGetSymbolAddress((void**)&y,    g_y);

    cudaFuncSetAttribute(attn_tc,
                         cudaFuncAttributeMaxDynamicSharedMemorySize,
                         ATTN_SMEM);

    dim3 gg(8, 64);   // N/128, M/128 for M=8192, N=1024

    gemm_tc<<<gg, 256>>>(query, w_qs, q, 8192, 1024, 1024, 1);
    gemm_tc<<<gg, 256>>>(key,   w_ks, k, 8192, 1024, 1024, 1);
    gemm_tc<<<gg, 256>>>(value, w_vs, v, 8192, 1024, 1024, 2);

    attn_tc<<<dim3(16, 16, 4), 128, ATTN_SMEM>>>(q, k, v, mask, attn);

    gemm_tc<<<gg, 256>>>(attn, w_out, y, 8192, 1024, 1024, 0);

    ln_kernel<<<8192, 256>>>(y, query, ln_g, ln_b, out);
}

// round 7
// speedup vs baseline: 3.7417x; 1.0018x over previous
#include <cuda_runtime.h>
#include <cuda_bf16.h>

// ---------------------------------------------------------------------------
// MultiHeadedAttention: B=4, S=2048, D_MODEL=1024, H=16, DK=DV=64
// Round 6: bf16 attention (ldmatrix + mma.m16n8k16, log2-domain softmax),
//          projections emit bf16; GEMM reverted to R4 shape (regression fix).
// ---------------------------------------------------------------------------

#define NEGV (-1e9f)
#define MINIT (-1e38f)

__device__ __nv_bfloat16 g_q[4 * 16 * 2048 * 64];
__device__ __nv_bfloat16 g_k[4 * 16 * 2048 * 64];
__device__ __nv_bfloat16 g_v[4 * 16 * 2048 * 64];   // V^T per head [B,H,64,2048]
__device__ float g_attn[8192 * 1024];
__device__ float g_y[8192 * 1024];

__device__ __forceinline__ unsigned f2tf(float f) {
    unsigned u;
    asm("cvt.rna.tf32.f32 %0, %1;" : "=r"(u) : "f"(f));
    return u;
}

__device__ __forceinline__ void mma_tf32(float c[4], const unsigned a[4],
                                         const unsigned b[2]) {
    asm volatile(
        "mma.sync.aligned.m16n8k8.row.col.f32.tf32.tf32.f32 "
        "{%0,%1,%2,%3}, {%4,%5,%6,%7}, {%8,%9}, {%0,%1,%2,%3};"
        : "+f"(c[0]), "+f"(c[1]), "+f"(c[2]), "+f"(c[3])
        : "r"(a[0]), "r"(a[1]), "r"(a[2]), "r"(a[3]), "r"(b[0]), "r"(b[1]));
}

__device__ __forceinline__ void mma_bf16(float c[4], const unsigned a[4],
                                         const unsigned b[2]) {
    asm volatile(
        "mma.sync.aligned.m16n8k16.row.col.f32.bf16.bf16.f32 "
        "{%0,%1,%2,%3}, {%4,%5,%6,%7}, {%8,%9}, {%0,%1,%2,%3};"
        : "+f"(c[0]), "+f"(c[1]), "+f"(c[2]), "+f"(c[3])
        : "r"(a[0]), "r"(a[1]), "r"(a[2]), "r"(a[3]), "r"(b[0]), "r"(b[1]));
}

__device__ __forceinline__ void ldsm4(unsigned& r0, unsigned& r1,
                                      unsigned& r2, unsigned& r3,
                                      const void* p) {
    unsigned a = (unsigned)__cvta_generic_to_shared(p);
    asm volatile(
        "ldmatrix.sync.aligned.m8n8.x4.shared.b16 {%0,%1,%2,%3}, [%4];"
        : "=r"(r0), "=r"(r1), "=r"(r2), "=r"(r3) : "r"(a));
}

__device__ __forceinline__ float ex2(float x) {
    float y;
    asm("ex2.approx.f32 %0, %1;" : "=f"(y) : "f"(x));
    return y;
}

__device__ __forceinline__ unsigned pack_bf16(float lo, float hi) {
    unsigned u;
    asm("cvt.rn.bf16x2.f32 %0, %1, %2;" : "=r"(u) : "f"(hi), "f"(lo));
    return u;
}

// ---------------------------------------------------------------------------
// tf32 GEMM (R4 shape: static smem, register prefetch, 2 barriers/iter).
// 128x128 tile, k-tile 32, 256 threads (8 warps, warp 64x32).
// mode 0: fp32 row-major. mode 1: bf16 [B,H,S,64]. mode 2: bf16 V^T [B,H,64,S].
// ---------------------------------------------------------------------------
__global__ void __launch_bounds__(256) gemm_tc(
    const float* __restrict__ A, const float* __restrict__ B,
    void* __restrict__ Cv, int M, int N, int K, int mode)
{
    __shared__ unsigned As[128 * 36];
    __shared__ unsigned Bs[32 * 132];

    int tid = threadIdx.x;
    int wid = tid >> 5, lane = tid & 31;
    int r = lane >> 2, c = lane & 3, g = lane >> 2;
    int m0 = blockIdx.y * 128, n0 = blockIdx.x * 128;
    int wm = (wid & 1) * 64, wn = (wid >> 1) * 32;

    int arow[4], acol[4], brow[4], bcol[4];
#pragma unroll
    for (int i = 0; i < 4; i++) {
        int lin = tid + i * 256;
        arow[i] = lin >> 3;  acol[i] = (lin & 7) << 2;
        brow[i] = lin >> 5;  bcol[i] = (lin & 31) << 2;
    }

    float acc[4][4][4];
#pragma unroll
    for (int mt = 0; mt < 4; mt++)
#pragma unroll
        for (int nt = 0; nt < 4; nt++)
#pragma unroll
            for (int i = 0; i < 4; i++) acc[mt][nt][i] = 0.f;

    float4 pa[4], pb[4];
#pragma unroll
    for (int i = 0; i < 4; i++) {
        pa[i] = *(const float4*)&A[(size_t)(m0 + arow[i]) * K + acol[i]];
        pb[i] = *(const float4*)&B[(size_t)brow[i] * N + n0 + bcol[i]];
    }

    for (int k0 = 0; k0 < K; k0 += 32) {
        __syncthreads();
#pragma unroll
        for (int i = 0; i < 4; i++) {
            uint4 ua = {f2tf(pa[i].x), f2tf(pa[i].y), f2tf(pa[i].z), f2tf(pa[i].w)};
            *(uint4*)&As[arow[i] * 36 + acol[i]] = ua;
            uint4 ub = {f2tf(pb[i].x), f2tf(pb[i].y), f2tf(pb[i].z), f2tf(pb[i].w)};
            *(uint4*)&Bs[brow[i] * 132 + bcol[i]] = ub;
        }
        if (k0 + 32 < K) {
#pragma unroll
            for (int i = 0; i < 4; i++) {
                pa[i] = *(const float4*)&A[(size_t)(m0 + arow[i]) * K + k0 + 32 + acol[i]];
                pb[i] = *(const float4*)&B[(size_t)(k0 + 32 + brow[i]) * N + n0 + bcol[i]];
            }
        }
        __syncthreads();

#pragma unroll
        for (int ks = 0; ks < 4; ks++) {
            int k8 = ks * 8;
            unsigned ua[4][4], ub[4][2];
#pragma unroll
            for (int mt = 0; mt < 4; mt++) {
                int rr = wm + mt * 16 + r;
                ua[mt][0] = As[rr * 36 + k8 + c];
                ua[mt][1] = As[(rr + 8) * 36 + k8 + c];
                ua[mt][2] = As[rr * 36 + k8 + c + 4];
                ua[mt][3] = As[(rr + 8) * 36 + k8 + c + 4];
            }
#pragma unroll
            for (int nt = 0; nt < 4; nt++) {
                int cn = wn + nt * 8 + g;
                ub[nt][0] = Bs[(k8 + c) * 132 + cn];
                ub[nt][1] = Bs[(k8 + c + 4) * 132 + cn];
            }
#pragma unroll
            for (int mt = 0; mt < 4; mt++)
#pragma unroll
                for (int nt = 0; nt < 4; nt++)
                    mma_tf32(acc[mt][nt], ua[mt], ub[nt]);
        }
    }

#pragma unroll
    for (int mt = 0; mt < 4; mt++) {
#pragma unroll
        for (int nt = 0; nt < 4; nt++) {
            int rr = m0 + wm + mt * 16 + r;
            int cc = n0 + wn + nt * 8 + 2 * c;
            float* a4 = acc[mt][nt];
            if (mode == 0) {
                float* C = (float*)Cv;
                *(float2*)&C[(size_t)rr * N + cc] = make_float2(a4[0], a4[1]);
                *(float2*)&C[(size_t)(rr + 8) * N + cc] = make_float2(a4[2], a4[3]);
            } else if (mode == 1) {
                __nv_bfloat16* C = (__nv_bfloat16*)Cv;
                int b = rr >> 11, s = rr & 2047;
                int h = cc >> 6, d = cc & 63;
                size_t idx = (((size_t)(b * 16 + h) * 2048 + s) << 6) + d;
                *(__nv_bfloat162*)&C[idx] = __floats2bfloat162_rn(a4[0], a4[1]);
                int b2 = (rr + 8) >> 11, s2 = (rr + 8) & 2047;
                size_t idx2 = (((size_t)(b2 * 16 + h) * 2048 + s2) << 6) + d;
                *(__nv_bfloat162*)&C[idx2] = __floats2bfloat162_rn(a4[2], a4[3]);
            } else {  // mode 2: bf16 V^T [B,H,64,2048]
                __nv_bfloat16* C = (__nv_bfloat16*)Cv;
                int b = rr >> 11, s = rr & 2047;
                int h = cc >> 6, d = cc & 63;
                size_t base = ((size_t)(b * 16 + h) * 64 + d) * 2048;
                C[base + s] = __float2bfloat16_rn(a4[0]);
                C[base + 2048 + s] = __float2bfloat16_rn(a4[1]);
                int b2 = (rr + 8) >> 11, s2 = (rr + 8) & 2047;
                size_t base2 = ((size_t)(b2 * 16 + h) * 64 + d) * 2048;
                C[base2 + s2] = __float2bfloat16_rn(a4[2]);
                C[base2 + 2048 + s2] = __float2bfloat16_rn(a4[3]);
            }
        }
    }
}

// ---------------------------------------------------------------------------
// Flash attention, bf16 mma.m16n8k16 + ldmatrix. grid (S/128, H, B), 128 thr.
// Warp owns 32 rows x 64 cols; register softmax in log2 domain.
// SMEM bf16 stride 72: Qs[128] Ks[64] Vs[64] Ps[128]  (54 KB)
// ---------------------------------------------------------------------------
#define SQ 72
#define ATTN_SMEM ((128 + 64 + 64 + 128) * SQ * 2)

__global__ void __launch_bounds__(128, 2) attn_tc(
    const __nv_bfloat16* __restrict__ Q, const __nv_bfloat16* __restrict__ Kg,
    const __nv_bfloat16* __restrict__ Vt, const int* __restrict__ mask,
    float* __restrict__ O)
{
    extern __shared__ __align__(16) __nv_bfloat16 smb[];
    __nv_bfloat16* Qs = smb;                 // 128 x 72
    __nv_bfloat16* Ks = Qs + 128 * SQ;       // 64 x 72  [key][d]
    __nv_bfloat16* Vs = Ks + 64 * SQ;        // 64 x 72  [dv][key]
    __nv_bfloat16* Ps = Vs + 64 * SQ;        // 128 x 72

    int tid = threadIdx.x;
    int wid = tid >> 5, lane = tid & 31;
    int r = lane >> 2, c = lane & 3;
    int qt = blockIdx.x, h = blockIdx.y, b = blockIdx.z;
    int qbase = qt * 128;
    int wm = wid * 32;

    const float SC = 0.125f * 1.44269504088896f;   // scale * log2(e)

    const __nv_bfloat16* qp  = Q  + (((size_t)(b * 16 + h) * 2048 + qbase) << 6);
    const __nv_bfloat16* kp0 = Kg + (((size_t)(b * 16 + h) * 2048) << 6);
    const __nv_bfloat16* vt0 = Vt + ((size_t)(b * 16 + h) * 64) * 2048;

    const int* mrow[2][2];
#pragma unroll
    for (int mt = 0; mt < 2; mt++)
#pragma unroll
        for (int hf = 0; hf < 2; hf++)
            mrow[mt][hf] = mask +
                ((size_t)(b * 2048 + qbase + wm + mt * 16 + r + hf * 8)) * 2048 +
                2 * c;

    // stage Q tile (128x64 bf16, raw copy)
#pragma unroll
    for (int i = 0; i < 8; i++) {
        int lin = tid + i * 128;
        int row = lin >> 3, ch = (lin & 7) << 3;
        *(uint4*)&Qs[row * SQ + ch] = *(const uint4*)&qp[row * 64 + ch];
    }

    // ldmatrix lane addressing
    int la_row = lane & 15;                  // + tile row base
    int la_col = (lane >> 4) << 3;           // 0 or 8 within k16
    int lb_row = ((lane >> 4) << 3) + (lane & 7);
    int lb_col = ((lane >> 3) & 1) << 3;

    float m_[2][2], l_[2][2];
#pragma unroll
    for (int mt = 0; mt < 2; mt++)
#pragma unroll
        for (int hf = 0; hf < 2; hf++) { m_[mt][hf] = MINIT; l_[mt][hf] = 0.f; }

    float oacc[2][8][4];
#pragma unroll
    for (int mt = 0; mt < 2; mt++)
#pragma unroll
        for (int nt = 0; nt < 8; nt++)
#pragma unroll
            for (int i = 0; i < 4; i++) oacc[mt][nt][i] = 0.f;

    for (int kb = 0; kb < 2048; kb += 64) {
        __syncthreads();
        // stage K [key][d] and V^T [dv][key] tiles (64x64 bf16 each)
#pragma unroll
        for (int i = 0; i < 4; i++) {
            int lin = tid + i * 128;
            int row = lin >> 3, ch = (lin & 7) << 3;
            *(uint4*)&Ks[row * SQ + ch] =
                *(const uint4*)&kp0[(size_t)(kb + row) * 64 + ch];
            *(uint4*)&Vs[row * SQ + ch] =
                *(const uint4*)&vt0[(size_t)row * 2048 + kb + ch];
        }
        __syncthreads();

        // ---- S = Q K^T ----
        float sacc[2][8][4];
#pragma unroll
        for (int mt = 0; mt < 2; mt++)
#pragma unroll
            for (int nt = 0; nt < 8; nt++)
#pragma unroll
                for (int i = 0; i < 4; i++) sacc[mt][nt][i] = 0.f;

#pragma unroll
        for (int ks = 0; ks < 4; ks++) {
            int k16 = ks * 16;
            unsigned ua[2][4], ubs[8][2];
#pragma unroll
            for (int mt = 0; mt < 2; mt++)
                ldsm4(ua[mt][0], ua[mt][1], ua[mt][2], ua[mt][3],
                      &Qs[(wm + mt * 16 + la_row) * SQ + k16 + la_col]);
#pragma unroll
            for (int nt2 = 0; nt2 < 4; nt2++) {
                unsigned r0, r1, r2, r3;
                ldsm4(r0, r1, r2, r3,
                      &Ks[(nt2 * 16 + lb_row) * SQ + k16 + lb_col]);
                ubs[nt2 * 2][0] = r0;  ubs[nt2 * 2][1] = r1;
                ubs[nt2 * 2 + 1][0] = r2;  ubs[nt2 * 2 + 1][1] = r3;
            }
#pragma unroll
            for (int mt = 0; mt < 2; mt++)
#pragma unroll
                for (int nt = 0; nt < 8; nt++)
                    mma_bf16(sacc[mt][nt], ua[mt], ubs[nt]);
        }

        // ---- mask + online softmax (log2 domain) ----
#pragma unroll
        for (int mt = 0; mt < 2; mt++) {
            float mx0 = m_[mt][0], mx1 = m_[mt][1];
#pragma unroll
            for (int nt = 0; nt < 8; nt++) {
                int2 mk0 = *(const int2*)(mrow[mt][0] + kb + nt * 8);
                int2 mk1 = *(const int2*)(mrow[mt][1] + kb + nt * 8);
                float s0 = mk0.x ? sacc[mt][nt][0] * SC : NEGV;
                float s1 = mk0.y ? sacc[mt][nt][1] * SC : NEGV;
                float s2 = mk1.x ? sacc[mt][nt][2] * SC : NEGV;
                float s3 = mk1.y ? sacc[mt][nt][3] * SC : NEGV;
                sacc[mt][nt][0] = s0; sacc[mt][nt][1] = s1;
                sacc[mt][nt][2] = s2; sacc[mt][nt][3] = s3;
                mx0 = fmaxf(mx0, fmaxf(s0, s1));
                mx1 = fmaxf(mx1, fmaxf(s2, s3));
            }
            mx0 = fmaxf(mx0, __shfl_xor_sync(0xffffffffu, mx0, 1));
            mx0 = fmaxf(mx0, __shfl_xor_sync(0xffffffffu, mx0, 2));
            mx1 = fmaxf(mx1, __shfl_xor_sync(0xffffffffu, mx1, 1));
            mx1 = fmaxf(mx1, __shfl_xor_sync(0xffffffffu, mx1, 2));

            float al0 = ex2(m_[mt][0] - mx0);
            float al1 = ex2(m_[mt][1] - mx1);
            float sum0 = 0.f, sum1 = 0.f;
            int rr = wm + mt * 16 + r;
#pragma unroll
            for (int nt = 0; nt < 8; nt++) {
                float p0 = ex2(sacc[mt][nt][0] - mx0);
                float p1 = ex2(sacc[mt][nt][1] - mx0);
                float p2 = ex2(sacc[mt][nt][2] - mx1);
                float p3 = ex2(sacc[mt][nt][3] - mx1);
                sum0 += p0 + p1;
                sum1 += p2 + p3;
                *(unsigned*)&Ps[rr * SQ + nt * 8 + 2 * c] = pack_bf16(p0, p1);
                *(unsigned*)&Ps[(rr + 8) * SQ + nt * 8 + 2 * c] = pack_bf16(p2, p3);
            }
            sum0 += __shfl_xor_sync(0xffffffffu, sum0, 1);
            sum0 += __shfl_xor_sync(0xffffffffu, sum0, 2);
            sum1 += __shfl_xor_sync(0xffffffffu, sum1, 1);
            sum1 += __shfl_xor_sync(0xffffffffu, sum1, 2);

            m_[mt][0] = mx0; m_[mt][1] = mx1;
            l_[mt][0] = l_[mt][0] * al0 + sum0;
            l_[mt][1] = l_[mt][1] * al1 + sum1;
#pragma unroll
            for (int nt = 0; nt < 8; nt++) {
                oacc[mt][nt][0] *= al0; oacc[mt][nt][1] *= al0;
                oacc[mt][nt][2] *= al1; oacc[mt][nt][3] *= al1;
            }
        }
        __syncwarp();   // Ps rows are warp-private

        // ---- O += P V ----
#pragma unroll
        for (int ks = 0; ks < 4; ks++) {
            int k16 = ks * 16;
            unsigned ua[2][4], ubs[8][2];
#pragma unroll
            for (int mt = 0; mt < 2; mt++)
                ldsm4(ua[mt][0], ua[mt][1], ua[mt][2], ua[mt][3],
                      &Ps[(wm + mt * 16 + la_row) * SQ + k16 + la_col]);
#pragma unroll
            for (int nt2 = 0; nt2 < 4; nt2++) {
                unsigned r0, r1, r2, r3;
                ldsm4(r0, r1, r2, r3,
                      &Vs[(nt2 * 16 + lb_row) * SQ + k16 + lb_col]);
                ubs[nt2 * 2][0] = r0;  ubs[nt2 * 2][1] = r1;
                ubs[nt2 * 2 + 1][0] = r2;  ubs[nt2 * 2 + 1][1] = r3;
            }
#pragma unroll
            for (int mt = 0; mt < 2; mt++)
#pragma unroll
                for (int nt = 0; nt < 8; nt++)
                    mma_bf16(oacc[mt][nt], ua[mt], ubs[nt]);
        }
    }

    // final normalize + write [B,S,H*64] fp32
#pragma unroll
    for (int mt = 0; mt < 2; mt++) {
        float l0 = 1.f / l_[mt][0];
        float l1 = 1.f / l_[mt][1];
        int rowg = qbase + wm + mt * 16 + r;
#pragma unroll
        for (int nt = 0; nt < 8; nt++) {
            int cc = h * 64 + nt * 8 + 2 * c;
            *(float2*)&O[(size_t)(b * 2048 + rowg) * 1024 + cc] =
                make_float2(oacc[mt][nt][0] * l0, oacc[mt][nt][1] * l0);
            *(float2*)&O[(size_t)(b * 2048 + rowg + 8) * 1024 + cc] =
                make_float2(oacc[mt][nt][2] * l1, oacc[mt][nt][3] * l1);
        }
    }
}

// ---------------------------------------------------------------------------
// residual + LayerNorm
// ---------------------------------------------------------------------------
__global__ void __launch_bounds__(256) ln_kernel(
    const float* __restrict__ Y, const float* __restrict__ R,
    const float* __restrict__ g, const float* __restrict__ bt,
    float* __restrict__ out)
{
    __shared__ float red[2][8];
    int row = blockIdx.x;
    int tid = threadIdx.x;
    int lane = tid & 31, wid = tid >> 5;

    float4 y4 = ((const float4*)(Y + (size_t)row * 1024))[tid];
    float4 r4 = ((const float4*)(R + (size_t)row * 1024))[tid];
    float x0 = y4.x + r4.x, x1 = y4.y + r4.y, x2 = y4.z + r4.z, x3 = y4.w + r4.w;

    float sum = x0 + x1 + x2 + x3;
    float sq  = x0 * x0 + x1 * x1 + x2 * x2 + x3 * x3;
#pragma unroll
    for (int off = 16; off > 0; off >>= 1) {
        sum += __shfl_xor_sync(0xffffffff, sum, off);
        sq  += __shfl_xor_sync(0xffffffff, sq,  off);
    }
    if (lane == 0) { red[0][wid] = sum; red[1][wid] = sq; }
    __syncthreads();
    if (tid == 0) {
        float ts = 0.f, tq = 0.f;
#pragma unroll
        for (int w = 0; w < 8; w++) { ts += red[0][w]; tq += red[1][w]; }
        red[0][0] = ts; red[1][0] = tq;
    }
    __syncthreads();
    float mu  = red[0][0] * (1.f / 1024.f);
    float var = red[1][0] * (1.f / 1024.f) - mu * mu;
    float rstd = rsqrtf(var + 1e-6f);

    float4 g4 = ((const float4*)g)[tid];
    float4 b4 = ((const float4*)bt)[tid];
    float4 o;
    o.x = (x0 - mu) * rstd * g4.x + b4.x;
    o.y = (x1 - mu) * rstd * g4.y + b4.y;
    o.z = (x2 - mu) * rstd * g4.z + b4.z;
    o.w = (x3 - mu) * rstd * g4.w + b4.w;
    ((float4*)(out + (size_t)row * 1024))[tid] = o;
}

// ---------------------------------------------------------------------------
extern "C" void kernel_launch(void* const* d_in, const int* in_sizes, int n_in,
                              void* d_out, int out_size)
{
    const float* query = (const float*)d_in[0];
    const float* key   = (const float*)d_in[1];
    const float* value = (const float*)d_in[2];
    const int*   mask  = (const int*)d_in[3];
    const float* w_qs  = (const float*)d_in[4];
    const float* w_ks  = (const float*)d_in[5];
    const float* w_vs  = (const float*)d_in[6];
    const float* w_out = (const float*)d_in[7];
    const float* ln_g  = (const float*)d_in[8];
    const float* ln_b  = (const float*)d_in[9];
    float* out = (float*)d_out;

    __nv_bfloat16 *q, *k, *v;
    float *attn, *y;
    cudaGetSymbolAddress((void**)&q,    g_q);
    cudaGetSymbolAddress((void**)&k,    g_k);
    cudaGetSymbolAddress((void**)&v,    g_v);
    cudaGetSymbolAddress((void**)&attn, g_attn);
    cudaGetSymbolAddress((void**)&y,    g_y);

    cudaFuncSetAttribute(attn_tc,
                         cudaFuncAttributeMaxDynamicSharedMemorySize,
                         ATTN_SMEM);

    dim3 gg(8, 64);   // N/128, M/128 for M=8192, N=1024

    gemm_tc<<<gg, 256>>>(query, w_qs, q, 8192, 1024, 1024, 1);
    gemm_tc<<<gg, 256>>>(key,   w_ks, k, 8192, 1024, 1024, 1);
    gemm_tc<<<gg, 256>>>(value, w_vs, v, 8192, 1024, 1024, 2);

    attn_tc<<<dim3(16, 16, 4), 128, ATTN_SMEM>>>(q, k, v, mask, attn);

    gemm_tc<<<gg, 256>>>(attn, w_out, y, 8192, 1024, 1024, 0);

    ln_kernel<<<8192, 256>>>(y, query, ln_g, ln_b, out);
}

// round 8
// speedup vs baseline: 3.7434x; 1.0004x over previous
#include <cuda_runtime.h>
#include <cuda_bf16.h>

// ---------------------------------------------------------------------------
// MultiHeadedAttention: B=4, S=2048, D_MODEL=1024, H=16, DK=DV=64
// Round 6: bf16 attention (ldmatrix + mma.m16n8k16, log2-domain softmax),
//          projections emit bf16; GEMM reverted to R4 shape (regression fix).
// ---------------------------------------------------------------------------

#define NEGV (-1e9f)
#define MINIT (-1e38f)

__device__ __nv_bfloat16 g_q[4 * 16 * 2048 * 64];
__device__ __nv_bfloat16 g_k[4 * 16 * 2048 * 64];
__device__ __nv_bfloat16 g_v[4 * 16 * 2048 * 64];   // V^T per head [B,H,64,2048]
__device__ float g_attn[8192 * 1024];
__device__ float g_y[8192 * 1024];

__device__ __forceinline__ unsigned f2tf(float f) {
    unsigned u;
    asm("cvt.rna.tf32.f32 %0, %1;" : "=r"(u) : "f"(f));
    return u;
}

__device__ __forceinline__ void mma_tf32(float c[4], const unsigned a[4],
                                         const unsigned b[2]) {
    asm volatile(
        "mma.sync.aligned.m16n8k8.row.col.f32.tf32.tf32.f32 "
        "{%0,%1,%2,%3}, {%4,%5,%6,%7}, {%8,%9}, {%0,%1,%2,%3};"
        : "+f"(c[0]), "+f"(c[1]), "+f"(c[2]), "+f"(c[3])
        : "r"(a[0]), "r"(a[1]), "r"(a[2]), "r"(a[3]), "r"(b[0]), "r"(b[1]));
}

__device__ __forceinline__ void mma_bf16(float c[4], const unsigned a[4],
                                         const unsigned b[2]) {
    asm volatile(
        "mma.sync.aligned.m16n8k16.row.col.f32.bf16.bf16.f32 "
        "{%0,%1,%2,%3}, {%4,%5,%6,%7}, {%8,%9}, {%0,%1,%2,%3};"
        : "+f"(c[0]), "+f"(c[1]), "+f"(c[2]), "+f"(c[3])
        : "r"(a[0]), "r"(a[1]), "r"(a[2]), "r"(a[3]), "r"(b[0]), "r"(b[1]));
}

__device__ __forceinline__ void ldsm4(unsigned& r0, unsigned& r1,
                                      unsigned& r2, unsigned& r3,
                                      const void* p) {
    unsigned a = (unsigned)__cvta_generic_to_shared(p);
    asm volatile(
        "ldmatrix.sync.aligned.m8n8.x4.shared.b16 {%0,%1,%2,%3}, [%4];"
        : "=r"(r0), "=r"(r1), "=r"(r2), "=r"(r3) : "r"(a));
}

__device__ __forceinline__ float ex2(float x) {
    float y;
    asm("ex2.approx.f32 %0, %1;" : "=f"(y) : "f"(x));
    return y;
}

__device__ __forceinline__ unsigned pack_bf16(float lo, float hi) {
    unsigned u;
    asm("cvt.rn.bf16x2.f32 %0, %1, %2;" : "=r"(u) : "f"(hi), "f"(lo));
    return u;
}

// ---------------------------------------------------------------------------
// tf32 GEMM (R4 shape: static smem, register prefetch, 2 barriers/iter).
// 128x128 tile, k-tile 32, 256 threads (8 warps, warp 64x32).
// mode 0: fp32 row-major. mode 1: bf16 [B,H,S,64]. mode 2: bf16 V^T [B,H,64,S].
// ---------------------------------------------------------------------------
__global__ void __launch_bounds__(256) gemm_tc(
    const float* __restrict__ A, const float* __restrict__ B,
    void* __restrict__ Cv, int M, int N, int K, int mode)
{
    __shared__ unsigned As[128 * 36];
    __shared__ unsigned Bs[32 * 132];

    int tid = threadIdx.x;
    int wid = tid >> 5, lane = tid & 31;
    int r = lane >> 2, c = lane & 3, g = lane >> 2;
    int m0 = blockIdx.y * 128, n0 = blockIdx.x * 128;
    int wm = (wid & 1) * 64, wn = (wid >> 1) * 32;

    int arow[4], acol[4], brow[4], bcol[4];
#pragma unroll
    for (int i = 0; i < 4; i++) {
        int lin = tid + i * 256;
        arow[i] = lin >> 3;  acol[i] = (lin & 7) << 2;
        brow[i] = lin >> 5;  bcol[i] = (lin & 31) << 2;
    }

    float acc[4][4][4];
#pragma unroll
    for (int mt = 0; mt < 4; mt++)
#pragma unroll
        for (int nt = 0; nt < 4; nt++)
#pragma unroll
            for (int i = 0; i < 4; i++) acc[mt][nt][i] = 0.f;

    float4 pa[4], pb[4];
#pragma unroll
    for (int i = 0; i < 4; i++) {
        pa[i] = *(const float4*)&A[(size_t)(m0 + arow[i]) * K + acol[i]];
        pb[i] = *(const float4*)&B[(size_t)brow[i] * N + n0 + bcol[i]];
    }

    for (int k0 = 0; k0 < K; k0 += 32) {
        __syncthreads();
#pragma unroll
        for (int i = 0; i < 4; i++) {
            uint4 ua = {f2tf(pa[i].x), f2tf(pa[i].y), f2tf(pa[i].z), f2tf(pa[i].w)};
            *(uint4*)&As[arow[i] * 36 + acol[i]] = ua;
            uint4 ub = {f2tf(pb[i].x), f2tf(pb[i].y), f2tf(pb[i].z), f2tf(pb[i].w)};
            *(uint4*)&Bs[brow[i] * 132 + bcol[i]] = ub;
        }
        if (k0 + 32 < K) {
#pragma unroll
            for (int i = 0; i < 4; i++) {
                pa[i] = *(const float4*)&A[(size_t)(m0 + arow[i]) * K + k0 + 32 + acol[i]];
                pb[i] = *(const float4*)&B[(size_t)(k0 + 32 + brow[i]) * N + n0 + bcol[i]];
            }
        }
        __syncthreads();

#pragma unroll
        for (int ks = 0; ks < 4; ks++) {
            int k8 = ks * 8;
            unsigned ua[4][4], ub[4][2];
#pragma unroll
            for (int mt = 0; mt < 4; mt++) {
                int rr = wm + mt * 16 + r;
                ua[mt][0] = As[rr * 36 + k8 + c];
                ua[mt][1] = As[(rr + 8) * 36 + k8 + c];
                ua[mt][2] = As[rr * 36 + k8 + c + 4];
                ua[mt][3] = As[(rr + 8) * 36 + k8 + c + 4];
            }
#pragma unroll
            for (int nt = 0; nt < 4; nt++) {
                int cn = wn + nt * 8 + g;
                ub[nt][0] = Bs[(k8 + c) * 132 + cn];
                ub[nt][1] = Bs[(k8 + c + 4) * 132 + cn];
            }
#pragma unroll
            for (int mt = 0; mt < 4; mt++)
#pragma unroll
                for (int nt = 0; nt < 4; nt++)
                    mma_tf32(acc[mt][nt], ua[mt], ub[nt]);
        }
    }

#pragma unroll
    for (int mt = 0; mt < 4; mt++) {
#pragma unroll
        for (int nt = 0; nt < 4; nt++) {
            int rr = m0 + wm + mt * 16 + r;
            int cc = n0 + wn + nt * 8 + 2 * c;
            float* a4 = acc[mt][nt];
            if (mode == 0) {
                float* C = (float*)Cv;
                *(float2*)&C[(size_t)rr * N + cc] = make_float2(a4[0], a4[1]);
                *(float2*)&C[(size_t)(rr + 8) * N + cc] = make_float2(a4[2], a4[3]);
            } else if (mode == 1) {
                __nv_bfloat16* C = (__nv_bfloat16*)Cv;
                int b = rr >> 11, s = rr & 2047;
                int h = cc >> 6, d = cc & 63;
                size_t idx = (((size_t)(b * 16 + h) * 2048 + s) << 6) + d;
                *(__nv_bfloat162*)&C[idx] = __floats2bfloat162_rn(a4[0], a4[1]);
                int b2 = (rr + 8) >> 11, s2 = (rr + 8) & 2047;
                size_t idx2 = (((size_t)(b2 * 16 + h) * 2048 + s2) << 6) + d;
                *(__nv_bfloat162*)&C[idx2] = __floats2bfloat162_rn(a4[2], a4[3]);
            } else {  // mode 2: bf16 V^T [B,H,64,2048]
                __nv_bfloat16* C = (__nv_bfloat16*)Cv;
                int b = rr >> 11, s = rr & 2047;
                int h = cc >> 6, d = cc & 63;
                size_t base = ((size_t)(b * 16 + h) * 64 + d) * 2048;
                C[base + s] = __float2bfloat16_rn(a4[0]);
                C[base + 2048 + s] = __float2bfloat16_rn(a4[1]);
                int b2 = (rr + 8) >> 11, s2 = (rr + 8) & 2047;
                size_t base2 = ((size_t)(b2 * 16 + h) * 64 + d) * 2048;
                C[base2 + s2] = __float2bfloat16_rn(a4[2]);
                C[base2 + 2048 + s2] = __float2bfloat16_rn(a4[3]);
            }
        }
    }
}

// ---------------------------------------------------------------------------
// Flash attention, bf16 mma.m16n8k16 + ldmatrix. grid (S/128, H, B), 128 thr.
// Warp owns 32 rows x 64 cols; register softmax in log2 domain.
// SMEM bf16 stride 72: Qs[128] Ks[64] Vs[64] Ps[128]  (54 KB)
// ---------------------------------------------------------------------------
#define SQ 72
#define ATTN_SMEM ((128 + 64 + 64 + 128) * SQ * 2)

__global__ void __launch_bounds__(128, 2) attn_tc(
    const __nv_bfloat16* __restrict__ Q, const __nv_bfloat16* __restrict__ Kg,
    const __nv_bfloat16* __restrict__ Vt, const int* __restrict__ mask,
    float* __restrict__ O)
{
    extern __shared__ __align__(16) __nv_bfloat16 smb[];
    __nv_bfloat16* Qs = smb;                 // 128 x 72
    __nv_bfloat16* Ks = Qs + 128 * SQ;       // 64 x 72  [key][d]
    __nv_bfloat16* Vs = Ks + 64 * SQ;        // 64 x 72  [dv][key]
    __nv_bfloat16* Ps = Vs + 64 * SQ;        // 128 x 72

    int tid = threadIdx.x;
    int wid = tid >> 5, lane = tid & 31;
    int r = lane >> 2, c = lane & 3;
    int qt = blockIdx.x, h = blockIdx.y, b = blockIdx.z;
    int qbase = qt * 128;
    int wm = wid * 32;

    const float SC = 0.125f * 1.44269504088896f;   // scale * log2(e)

    const __nv_bfloat16* qp  = Q  + (((size_t)(b * 16 + h) * 2048 + qbase) << 6);
    const __nv_bfloat16* kp0 = Kg + (((size_t)(b * 16 + h) * 2048) << 6);
    const __nv_bfloat16* vt0 = Vt + ((size_t)(b * 16 + h) * 64) * 2048;

    const int* mrow[2][2];
#pragma unroll
    for (int mt = 0; mt < 2; mt++)
#pragma unroll
        for (int hf = 0; hf < 2; hf++)
            mrow[mt][hf] = mask +
                ((size_t)(b * 2048 + qbase + wm + mt * 16 + r + hf * 8)) * 2048 +
                2 * c;

    // stage Q tile (128x64 bf16, raw copy)
#pragma unroll
    for (int i = 0; i < 8; i++) {
        int lin = tid + i * 128;
        int row = lin >> 3, ch = (lin & 7) << 3;
        *(uint4*)&Qs[row * SQ + ch] = *(const uint4*)&qp[row * 64 + ch];
    }

    // ldmatrix lane addressing
    int la_row = lane & 15;                  // + tile row base
    int la_col = (lane >> 4) << 3;           // 0 or 8 within k16
    int lb_row = ((lane >> 4) << 3) + (lane & 7);
    int lb_col = ((lane >> 3) & 1) << 3;

    float m_[2][2], l_[2][2];
#pragma unroll
    for (int mt = 0; mt < 2; mt++)
#pragma unroll
        for (int hf = 0; hf < 2; hf++) { m_[mt][hf] = MINIT; l_[mt][hf] = 0.f; }

    float oacc[2][8][4];
#pragma unroll
    for (int mt = 0; mt < 2; mt++)
#pragma unroll
        for (int nt = 0; nt < 8; nt++)
#pragma unroll
            for (int i = 0; i < 4; i++) oacc[mt][nt][i] = 0.f;

    for (int kb = 0; kb < 2048; kb += 64) {
        __syncthreads();
        // stage K [key][d] and V^T [dv][key] tiles (64x64 bf16 each)
#pragma unroll
        for (int i = 0; i < 4; i++) {
            int lin = tid + i * 128;
            int row = lin >> 3, ch = (lin & 7) << 3;
            *(uint4*)&Ks[row * SQ + ch] =
                *(const uint4*)&kp0[(size_t)(kb + row) * 64 + ch];
            *(uint4*)&Vs[row * SQ + ch] =
                *(const uint4*)&vt0[(size_t)row * 2048 + kb + ch];
        }
        __syncthreads();

        // ---- S = Q K^T ----
        float sacc[2][8][4];
#pragma unroll
        for (int mt = 0; mt < 2; mt++)
#pragma unroll
            for (int nt = 0; nt < 8; nt++)
#pragma unroll
                for (int i = 0; i < 4; i++) sacc[mt][nt][i] = 0.f;

#pragma unroll
        for (int ks = 0; ks < 4; ks++) {
            int k16 = ks * 16;
            unsigned ua[2][4], ubs[8][2];
#pragma unroll
            for (int mt = 0; mt < 2; mt++)
                ldsm4(ua[mt][0], ua[mt][1], ua[mt][2], ua[mt][3],
                      &Qs[(wm + mt * 16 + la_row) * SQ + k16 + la_col]);
#pragma unroll
            for (int nt2 = 0; nt2 < 4; nt2++) {
                unsigned r0, r1, r2, r3;
                ldsm4(r0, r1, r2, r3,
                      &Ks[(nt2 * 16 + lb_row) * SQ + k16 + lb_col]);
                ubs[nt2 * 2][0] = r0;  ubs[nt2 * 2][1] = r1;
                ubs[nt2 * 2 + 1][0] = r2;  ubs[nt2 * 2 + 1][1] = r3;
            }
#pragma unroll
            for (int mt = 0; mt < 2; mt++)
#pragma unroll
                for (int nt = 0; nt < 8; nt++)
                    mma_bf16(sacc[mt][nt], ua[mt], ubs[nt]);
        }

        // ---- mask + online softmax (log2 domain) ----
#pragma unroll
        for (int mt = 0; mt < 2; mt++) {
            float mx0 = m_[mt][0], mx1 = m_[mt][1];
#pragma unroll
            for (int nt = 0; nt < 8; nt++) {
                int2 mk0 = *(const int2*)(mrow[mt][0] + kb + nt * 8);
                int2 mk1 = *(const int2*)(mrow[mt][1] + kb + nt * 8);
                float s0 = mk0.x ? sacc[mt][nt][0] * SC : NEGV;
                float s1 = mk0.y ? sacc[mt][nt][1] * SC : NEGV;
                float s2 = mk1.x ? sacc[mt][nt][2] * SC : NEGV;
                float s3 = mk1.y ? sacc[mt][nt][3] * SC : NEGV;
                sacc[mt][nt][0] = s0; sacc[mt][nt][1] = s1;
                sacc[mt][nt][2] = s2; sacc[mt][nt][3] = s3;
                mx0 = fmaxf(mx0, fmaxf(s0, s1));
                mx1 = fmaxf(mx1, fmaxf(s2, s3));
            }
            mx0 = fmaxf(mx0, __shfl_xor_sync(0xffffffffu, mx0, 1));
            mx0 = fmaxf(mx0, __shfl_xor_sync(0xffffffffu, mx0, 2));
            mx1 = fmaxf(mx1, __shfl_xor_sync(0xffffffffu, mx1, 1));
            mx1 = fmaxf(mx1, __shfl_xor_sync(0xffffffffu, mx1, 2));

            float al0 = ex2(m_[mt][0] - mx0);
            float al1 = ex2(m_[mt][1] - mx1);
            float sum0 = 0.f, sum1 = 0.f;
            int rr = wm + mt * 16 + r;
#pragma unroll
            for (int nt = 0; nt < 8; nt++) {
                float p0 = ex2(sacc[mt][nt][0] - mx0);
                float p1 = ex2(sacc[mt][nt][1] - mx0);
                float p2 = ex2(sacc[mt][nt][2] - mx1);
                float p3 = ex2(sacc[mt][nt][3] - mx1);
                sum0 += p0 + p1;
                sum1 += p2 + p3;
                *(unsigned*)&Ps[rr * SQ + nt * 8 + 2 * c] = pack_bf16(p0, p1);
                *(unsigned*)&Ps[(rr + 8) * SQ + nt * 8 + 2 * c] = pack_bf16(p2, p3);
            }
            sum0 += __shfl_xor_sync(0xffffffffu, sum0, 1);
            sum0 += __shfl_xor_sync(0xffffffffu, sum0, 2);
            sum1 += __shfl_xor_sync(0xffffffffu, sum1, 1);
            sum1 += __shfl_xor_sync(0xffffffffu, sum1, 2);

            m_[mt][0] = mx0; m_[mt][1] = mx1;
            l_[mt][0] = l_[mt][0] * al0 + sum0;
            l_[mt][1] = l_[mt][1] * al1 + sum1;
#pragma unroll
            for (int nt = 0; nt < 8; nt++) {
                oacc[mt][nt][0] *= al0; oacc[mt][nt][1] *= al0;
                oacc[mt][nt][2] *= al1; oacc[mt][nt][3] *= al1;
            }
        }
        __syncwarp();   // Ps rows are warp-private

        // ---- O += P V ----
#pragma unroll
        for (int ks = 0; ks < 4; ks++) {
            int k16 = ks * 16;
            unsigned ua[2][4], ubs[8][2];
#pragma unroll
            for (int mt = 0; mt < 2; mt++)
                ldsm4(ua[mt][0], ua[mt][1], ua[mt][2], ua[mt][3],
                      &Ps[(wm + mt * 16 + la_row) * SQ + k16 + la_col]);
#pragma unroll
            for (int nt2 = 0; nt2 < 4; nt2++) {
                unsigned r0, r1, r2, r3;
                ldsm4(r0, r1, r2, r3,
                      &Vs[(nt2 * 16 + lb_row) * SQ + k16 + lb_col]);
                ubs[nt2 * 2][0] = r0;  ubs[nt2 * 2][1] = r1;
                ubs[nt2 * 2 + 1][0] = r2;  ubs[nt2 * 2 + 1][1] = r3;
            }
#pragma unroll
            for (int mt = 0; mt < 2; mt++)
#pragma unroll
                for (int nt = 0; nt < 8; nt++)
                    mma_bf16(oacc[mt][nt], ua[mt], ubs[nt]);
        }
    }

    // final normalize + write [B,S,H*64] fp32
#pragma unroll
    for (int mt = 0; mt < 2; mt++) {
        float l0 = 1.f / l_[mt][0];
        float l1 = 1.f / l_[mt][1];
        int rowg = qbase + wm + mt * 16 + r;
#pragma unroll
        for (int nt = 0; nt < 8; nt++) {
            int cc = h * 64 + nt * 8 + 2 * c;
            *(float2*)&O[(size_t)(b * 2048 + rowg) * 1024 + cc] =
                make_float2(oacc[mt][nt][0] * l0, oacc[mt][nt][1] * l0);
            *(float2*)&O[(size_t)(b * 2048 + rowg + 8) * 1024 + cc] =
                make_float2(oacc[mt][nt][2] * l1, oacc[mt][nt][3] * l1);
        }
    }
}

// ---------------------------------------------------------------------------
// residual + LayerNorm
// ---------------------------------------------------------------------------
__global__ void __launch_bounds__(256) ln_kernel(
    const float* __restrict__ Y, const float* __restrict__ R,
    const float* __restrict__ g, const float* __restrict__ bt,
    float* __restrict__ out)
{
    __shared__ float red[2][8];
    int row = blockIdx.x;
    int tid = threadIdx.x;
    int lane = tid & 31, wid = tid >> 5;

    float4 y4 = ((const float4*)(Y + (size_t)row * 1024))[tid];
    float4 r4 = ((const float4*)(R + (size_t)row * 1024))[tid];
    float x0 = y4.x + r4.x, x1 = y4.y + r4.y, x2 = y4.z + r4.z, x3 = y4.w + r4.w;

    float sum = x0 + x1 + x2 + x3;
    float sq  = x0 * x0 + x1 * x1 + x2 * x2 + x3 * x3;
#pragma unroll
    for (int off = 16; off > 0; off >>= 1) {
        sum += __shfl_xor_sync(0xffffffff, sum, off);
        sq  += __shfl_xor_sync(0xffffffff, sq,  off);
    }
    if (lane == 0) { red[0][wid] = sum; red[1][wid] = sq; }
    __syncthreads();
    if (tid == 0) {
        float ts = 0.f, tq = 0.f;
#pragma unroll
        for (int w = 0; w < 8; w++) { ts += red[0][w]; tq += red[1][w]; }
        red[0][0] = ts; red[1][0] = tq;
    }
    __syncthreads();
    float mu  = red[0][0] * (1.f / 1024.f);
    float var = red[1][0] * (1.f / 1024.f) - mu * mu;
    float rstd = rsqrtf(var + 1e-6f);

    float4 g4 = ((const float4*)g)[tid];
    float4 b4 = ((const float4*)bt)[tid];
    float4 o;
    o.x = (x0 - mu) * rstd * g4.x + b4.x;
    o.y = (x1 - mu) * rstd * g4.y + b4.y;
    o.z = (x2 - mu) * rstd * g4.z + b4.z;
    o.w = (x3 - mu) * rstd * g4.w + b4.w;
    ((float4*)(out + (size_t)row * 1024))[tid] = o;
}

// ---------------------------------------------------------------------------
extern "C" void kernel_launch(void* const* d_in, const int* in_sizes, int n_in,
                              void* d_out, int out_size)
{
    const float* query = (const float*)d_in[0];
    const float* key   = (const float*)d_in[1];
    const float* value = (const float*)d_in[2];
    const int*   mask  = (const int*)d_in[3];
    const float* w_qs  = (const float*)d_in[4];
    const float* w_ks  = (const float*)d_in[5];
    const float* w_vs  = (const float*)d_in[6];
    const float* w_out = (const float*)d_in[7];
    const float* ln_g  = (const float*)d_in[8];
    const float* ln_b  = (const float*)d_in[9];
    float* out = (float*)d_out;

    __nv_bfloat16 *q, *k, *v;
    float *attn, *y;
    cudaGetSymbolAddress((void**)&q,    g_q);
    cudaGetSymbolAddress((void**)&k,    g_k);
    cudaGetSymbolAddress((void**)&v,    g_v);
    cudaGetSymbolAddress((void**)&attn, g_attn);
    cudaGetSymbolAddress((void**)&y,    g_y);

    cudaFuncSetAttribute(attn_tc,
                         cudaFuncAttributeMaxDynamicSharedMemorySize,
                         ATTN_SMEM);

    dim3 gg(8, 64);   // N/128, M/128 for M=8192, N=1024

    gemm_tc<<<gg, 256>>>(query, w_qs, q, 8192, 1024, 1024, 1);
    gemm_tc<<<gg, 256>>>(key,   w_ks, k, 8192, 1024, 1024, 1);
    gemm_tc<<<gg, 256>>>(value, w_vs, v, 8192, 1024, 1024, 2);

    attn_tc<<<dim3(16, 16, 4), 128, ATTN_SMEM>>>(q, k, v, mask, attn);

    gemm_tc<<<gg, 256>>>(attn, w_out, y, 8192, 1024, 1024, 0);

    ln_kernel<<<8192, 256>>>(y, query, ln_g, ln_b, out);
}

// round 9
// speedup vs baseline: 3.7523x; 1.0024x over previous
#include <cuda_runtime.h>
#include <cuda_bf16.h>

// ---------------------------------------------------------------------------
// MultiHeadedAttention: B=4, S=2048, D_MODEL=1024, H=16, DK=DV=64
// Round 6: bf16 attention (ldmatrix + mma.m16n8k16, log2-domain softmax),
//          projections emit bf16; GEMM reverted to R4 shape (regression fix).
// ---------------------------------------------------------------------------

#define NEGV (-1e9f)
#define MINIT (-1e38f)

__device__ __nv_bfloat16 g_q[4 * 16 * 2048 * 64];
__device__ __nv_bfloat16 g_k[4 * 16 * 2048 * 64];
__device__ __nv_bfloat16 g_v[4 * 16 * 2048 * 64];   // V^T per head [B,H,64,2048]
__device__ float g_attn[8192 * 1024];
__device__ float g_y[8192 * 1024];

__device__ __forceinline__ unsigned f2tf(float f) {
    unsigned u;
    asm("cvt.rna.tf32.f32 %0, %1;" : "=r"(u) : "f"(f));
    return u;
}

__device__ __forceinline__ void mma_tf32(float c[4], const unsigned a[4],
                                         const unsigned b[2]) {
    asm volatile(
        "mma.sync.aligned.m16n8k8.row.col.f32.tf32.tf32.f32 "
        "{%0,%1,%2,%3}, {%4,%5,%6,%7}, {%8,%9}, {%0,%1,%2,%3};"
        : "+f"(c[0]), "+f"(c[1]), "+f"(c[2]), "+f"(c[3])
        : "r"(a[0]), "r"(a[1]), "r"(a[2]), "r"(a[3]), "r"(b[0]), "r"(b[1]));
}

__device__ __forceinline__ void mma_bf16(float c[4], const unsigned a[4],
                                         const unsigned b[2]) {
    asm volatile(
        "mma.sync.aligned.m16n8k16.row.col.f32.bf16.bf16.f32 "
        "{%0,%1,%2,%3}, {%4,%5,%6,%7}, {%8,%9}, {%0,%1,%2,%3};"
        : "+f"(c[0]), "+f"(c[1]), "+f"(c[2]), "+f"(c[3])
        : "r"(a[0]), "r"(a[1]), "r"(a[2]), "r"(a[3]), "r"(b[0]), "r"(b[1]));
}

__device__ __forceinline__ void ldsm4(unsigned& r0, unsigned& r1,
                                      unsigned& r2, unsigned& r3,
                                      const void* p) {
    unsigned a = (unsigned)__cvta_generic_to_shared(p);
    asm volatile(
        "ldmatrix.sync.aligned.m8n8.x4.shared.b16 {%0,%1,%2,%3}, [%4];"
        : "=r"(r0), "=r"(r1), "=r"(r2), "=r"(r3) : "r"(a));
}

__device__ __forceinline__ float ex2(float x) {
    float y;
    asm("ex2.approx.f32 %0, %1;" : "=f"(y) : "f"(x));
    return y;
}

__device__ __forceinline__ unsigned pack_bf16(float lo, float hi) {
    unsigned u;
    asm("cvt.rn.bf16x2.f32 %0, %1, %2;" : "=r"(u) : "f"(hi), "f"(lo));
    return u;
}

// ---------------------------------------------------------------------------
// tf32 GEMM (R4 shape: static smem, register prefetch, 2 barriers/iter).
// 128x128 tile, k-tile 32, 256 threads (8 warps, warp 64x32).
// mode 0: fp32 row-major. mode 1: bf16 [B,H,S,64]. mode 2: bf16 V^T [B,H,64,S].
// ---------------------------------------------------------------------------
__global__ void __launch_bounds__(256) gemm_tc(
    const float* __restrict__ A, const float* __restrict__ B,
    void* __restrict__ Cv, int M, int N, int K, int mode)
{
    __shared__ unsigned As[128 * 36];
    __shared__ unsigned Bs[32 * 132];

    int tid = threadIdx.x;
    int wid = tid >> 5, lane = tid & 31;
    int r = lane >> 2, c = lane & 3, g = lane >> 2;
    int m0 = blockIdx.y * 128, n0 = blockIdx.x * 128;
    int wm = (wid & 1) * 64, wn = (wid >> 1) * 32;

    int arow[4], acol[4], brow[4], bcol[4];
#pragma unroll
    for (int i = 0; i < 4; i++) {
        int lin = tid + i * 256;
        arow[i] = lin >> 3;  acol[i] = (lin & 7) << 2;
        brow[i] = lin >> 5;  bcol[i] = (lin & 31) << 2;
    }

    float acc[4][4][4];
#pragma unroll
    for (int mt = 0; mt < 4; mt++)
#pragma unroll
        for (int nt = 0; nt < 4; nt++)
#pragma unroll
            for (int i = 0; i < 4; i++) acc[mt][nt][i] = 0.f;

    float4 pa[4], pb[4];
#pragma unroll
    for (int i = 0; i < 4; i++) {
        pa[i] = *(const float4*)&A[(size_t)(m0 + arow[i]) * K + acol[i]];
        pb[i] = *(const float4*)&B[(size_t)brow[i] * N + n0 + bcol[i]];
    }

    for (int k0 = 0; k0 < K; k0 += 32) {
        __syncthreads();
#pragma unroll
        for (int i = 0; i < 4; i++) {
            uint4 ua = {f2tf(pa[i].x), f2tf(pa[i].y), f2tf(pa[i].z), f2tf(pa[i].w)};
            *(uint4*)&As[arow[i] * 36 + acol[i]] = ua;
            uint4 ub = {f2tf(pb[i].x), f2tf(pb[i].y), f2tf(pb[i].z), f2tf(pb[i].w)};
            *(uint4*)&Bs[brow[i] * 132 + bcol[i]] = ub;
        }
        if (k0 + 32 < K) {
#pragma unroll
            for (int i = 0; i < 4; i++) {
                pa[i] = *(const float4*)&A[(size_t)(m0 + arow[i]) * K + k0 + 32 + acol[i]];
                pb[i] = *(const float4*)&B[(size_t)(k0 + 32 + brow[i]) * N + n0 + bcol[i]];
            }
        }
        __syncthreads();

#pragma unroll
        for (int ks = 0; ks < 4; ks++) {
            int k8 = ks * 8;
            unsigned ua[4][4], ub[4][2];
#pragma unroll
            for (int mt = 0; mt < 4; mt++) {
                int rr = wm + mt * 16 + r;
                ua[mt][0] = As[rr * 36 + k8 + c];
                ua[mt][1] = As[(rr + 8) * 36 + k8 + c];
                ua[mt][2] = As[rr * 36 + k8 + c + 4];
                ua[mt][3] = As[(rr + 8) * 36 + k8 + c + 4];
            }
#pragma unroll
            for (int nt = 0; nt < 4; nt++) {
                int cn = wn + nt * 8 + g;
                ub[nt][0] = Bs[(k8 + c) * 132 + cn];
                ub[nt][1] = Bs[(k8 + c + 4) * 132 + cn];
            }
#pragma unroll
            for (int mt = 0; mt < 4; mt++)
#pragma unroll
                for (int nt = 0; nt < 4; nt++)
                    mma_tf32(acc[mt][nt], ua[mt], ub[nt]);
        }
    }

#pragma unroll
    for (int mt = 0; mt < 4; mt++) {
#pragma unroll
        for (int nt = 0; nt < 4; nt++) {
            int rr = m0 + wm + mt * 16 + r;
            int cc = n0 + wn + nt * 8 + 2 * c;
            float* a4 = acc[mt][nt];
            if (mode == 0) {
                float* C = (float*)Cv;
                *(float2*)&C[(size_t)rr * N + cc] = make_float2(a4[0], a4[1]);
                *(float2*)&C[(size_t)(rr + 8) * N + cc] = make_float2(a4[2], a4[3]);
            } else if (mode == 1) {
                __nv_bfloat16* C = (__nv_bfloat16*)Cv;
                int b = rr >> 11, s = rr & 2047;
                int h = cc >> 6, d = cc & 63;
                size_t idx = (((size_t)(b * 16 + h) * 2048 + s) << 6) + d;
                *(__nv_bfloat162*)&C[idx] = __floats2bfloat162_rn(a4[0], a4[1]);
                int b2 = (rr + 8) >> 11, s2 = (rr + 8) & 2047;
                size_t idx2 = (((size_t)(b2 * 16 + h) * 2048 + s2) << 6) + d;
                *(__nv_bfloat162*)&C[idx2] = __floats2bfloat162_rn(a4[2], a4[3]);
            } else {  // mode 2: bf16 V^T [B,H,64,2048]
                __nv_bfloat16* C = (__nv_bfloat16*)Cv;
                int b = rr >> 11, s = rr & 2047;
                int h = cc >> 6, d = cc & 63;
                size_t base = ((size_t)(b * 16 + h) * 64 + d) * 2048;
                C[base + s] = __float2bfloat16_rn(a4[0]);
                C[base + 2048 + s] = __float2bfloat16_rn(a4[1]);
                int b2 = (rr + 8) >> 11, s2 = (rr + 8) & 2047;
                size_t base2 = ((size_t)(b2 * 16 + h) * 64 + d) * 2048;
                C[base2 + s2] = __float2bfloat16_rn(a4[2]);
                C[base2 + 2048 + s2] = __float2bfloat16_rn(a4[3]);
            }
        }
    }
}

// ---------------------------------------------------------------------------
// Flash attention, bf16 mma.m16n8k16 + ldmatrix. grid (S/128, H, B), 128 thr.
// Warp owns 32 rows x 64 cols; register softmax in log2 domain.
// SMEM bf16 stride 72: Qs[128] Ks[64] Vs[64] Ps[128]  (54 KB)
// ---------------------------------------------------------------------------
#define SQ 72
#define ATTN_SMEM ((128 + 64 + 64 + 128) * SQ * 2)

__global__ void __launch_bounds__(128, 2) attn_tc(
    const __nv_bfloat16* __restrict__ Q, const __nv_bfloat16* __restrict__ Kg,
    const __nv_bfloat16* __restrict__ Vt, const int* __restrict__ mask,
    float* __restrict__ O)
{
    extern __shared__ __align__(16) __nv_bfloat16 smb[];
    __nv_bfloat16* Qs = smb;                 // 128 x 72
    __nv_bfloat16* Ks = Qs + 128 * SQ;       // 64 x 72  [key][d]
    __nv_bfloat16* Vs = Ks + 64 * SQ;        // 64 x 72  [dv][key]
    __nv_bfloat16* Ps = Vs + 64 * SQ;        // 128 x 72

    int tid = threadIdx.x;
    int wid = tid >> 5, lane = tid & 31;
    int r = lane >> 2, c = lane & 3;
    int qt = blockIdx.x, h = blockIdx.y, b = blockIdx.z;
    int qbase = qt * 128;
    int wm = wid * 32;

    const float SC = 0.125f * 1.44269504088896f;   // scale * log2(e)

    const __nv_bfloat16* qp  = Q  + (((size_t)(b * 16 + h) * 2048 + qbase) << 6);
    const __nv_bfloat16* kp0 = Kg + (((size_t)(b * 16 + h) * 2048) << 6);
    const __nv_bfloat16* vt0 = Vt + ((size_t)(b * 16 + h) * 64) * 2048;

    const int* mrow[2][2];
#pragma unroll
    for (int mt = 0; mt < 2; mt++)
#pragma unroll
        for (int hf = 0; hf < 2; hf++)
            mrow[mt][hf] = mask +
                ((size_t)(b * 2048 + qbase + wm + mt * 16 + r + hf * 8)) * 2048 +
                2 * c;

    // stage Q tile (128x64 bf16, raw copy)
#pragma unroll
    for (int i = 0; i < 8; i++) {
        int lin = tid + i * 128;
        int row = lin >> 3, ch = (lin & 7) << 3;
        *(uint4*)&Qs[row * SQ + ch] = *(const uint4*)&qp[row * 64 + ch];
    }

    // ldmatrix lane addressing
    int la_row = lane & 15;                  // + tile row base
    int la_col = (lane >> 4) << 3;           // 0 or 8 within k16
    int lb_row = ((lane >> 4) << 3) + (lane & 7);
    int lb_col = ((lane >> 3) & 1) << 3;

    float m_[2][2], l_[2][2];
#pragma unroll
    for (int mt = 0; mt < 2; mt++)
#pragma unroll
        for (int hf = 0; hf < 2; hf++) { m_[mt][hf] = MINIT; l_[mt][hf] = 0.f; }

    float oacc[2][8][4];
#pragma unroll
    for (int mt = 0; mt < 2; mt++)
#pragma unroll
        for (int nt = 0; nt < 8; nt++)
#pragma unroll
            for (int i = 0; i < 4; i++) oacc[mt][nt][i] = 0.f;

    for (int kb = 0; kb < 2048; kb += 64) {
        __syncthreads();
        // stage K [key][d] and V^T [dv][key] tiles (64x64 bf16 each)
#pragma unroll
        for (int i = 0; i < 4; i++) {
            int lin = tid + i * 128;
            int row = lin >> 3, ch = (lin & 7) << 3;
            *(uint4*)&Ks[row * SQ + ch] =
                *(const uint4*)&kp0[(size_t)(kb + row) * 64 + ch];
            *(uint4*)&Vs[row * SQ + ch] =
                *(const uint4*)&vt0[(size_t)row * 2048 + kb + ch];
        }
        __syncthreads();

        // ---- S = Q K^T ----
        float sacc[2][8][4];
#pragma unroll
        for (int mt = 0; mt < 2; mt++)
#pragma unroll
            for (int nt = 0; nt < 8; nt++)
#pragma unroll
                for (int i = 0; i < 4; i++) sacc[mt][nt][i] = 0.f;

#pragma unroll
        for (int ks = 0; ks < 4; ks++) {
            int k16 = ks * 16;
            unsigned ua[2][4], ubs[8][2];
#pragma unroll
            for (int mt = 0; mt < 2; mt++)
                ldsm4(ua[mt][0], ua[mt][1], ua[mt][2], ua[mt][3],
                      &Qs[(wm + mt * 16 + la_row) * SQ + k16 + la_col]);
#pragma unroll
            for (int nt2 = 0; nt2 < 4; nt2++) {
                unsigned r0, r1, r2, r3;
                ldsm4(r0, r1, r2, r3,
                      &Ks[(nt2 * 16 + lb_row) * SQ + k16 + lb_col]);
                ubs[nt2 * 2][0] = r0;  ubs[nt2 * 2][1] = r1;
                ubs[nt2 * 2 + 1][0] = r2;  ubs[nt2 * 2 + 1][1] = r3;
            }
#pragma unroll
            for (int mt = 0; mt < 2; mt++)
#pragma unroll
                for (int nt = 0; nt < 8; nt++)
                    mma_bf16(sacc[mt][nt], ua[mt], ubs[nt]);
        }

        // ---- mask + online softmax (log2 domain) ----
#pragma unroll
        for (int mt = 0; mt < 2; mt++) {
            float mx0 = m_[mt][0], mx1 = m_[mt][1];
#pragma unroll
            for (int nt = 0; nt < 8; nt++) {
                int2 mk0 = *(const int2*)(mrow[mt][0] + kb + nt * 8);
                int2 mk1 = *(const int2*)(mrow[mt][1] + kb + nt * 8);
                float s0 = mk0.x ? sacc[mt][nt][0] * SC : NEGV;
                float s1 = mk0.y ? sacc[mt][nt][1] * SC : NEGV;
                float s2 = mk1.x ? sacc[mt][nt][2] * SC : NEGV;
                float s3 = mk1.y ? sacc[mt][nt][3] * SC : NEGV;
                sacc[mt][nt][0] = s0; sacc[mt][nt][1] = s1;
                sacc[mt][nt][2] = s2; sacc[mt][nt][3] = s3;
                mx0 = fmaxf(mx0, fmaxf(s0, s1));
                mx1 = fmaxf(mx1, fmaxf(s2, s3));
            }
            mx0 = fmaxf(mx0, __shfl_xor_sync(0xffffffffu, mx0, 1));
            mx0 = fmaxf(mx0, __shfl_xor_sync(0xffffffffu, mx0, 2));
            mx1 = fmaxf(mx1, __shfl_xor_sync(0xffffffffu, mx1, 1));
            mx1 = fmaxf(mx1, __shfl_xor_sync(0xffffffffu, mx1, 2));

            float al0 = ex2(m_[mt][0] - mx0);
            float al1 = ex2(m_[mt][1] - mx1);
            float sum0 = 0.f, sum1 = 0.f;
            int rr = wm + mt * 16 + r;
#pragma unroll
            for (int nt = 0; nt < 8; nt++) {
                float p0 = ex2(sacc[mt][nt][0] - mx0);
                float p1 = ex2(sacc[mt][nt][1] - mx0);
                float p2 = ex2(sacc[mt][nt][2] - mx1);
                float p3 = ex2(sacc[mt][nt][3] - mx1);
                sum0 += p0 + p1;
                sum1 += p2 + p3;
                *(unsigned*)&Ps[rr * SQ + nt * 8 + 2 * c] = pack_bf16(p0, p1);
                *(unsigned*)&Ps[(rr + 8) * SQ + nt * 8 + 2 * c] = pack_bf16(p2, p3);
            }
            sum0 += __shfl_xor_sync(0xffffffffu, sum0, 1);
            sum0 += __shfl_xor_sync(0xffffffffu, sum0, 2);
            sum1 += __shfl_xor_sync(0xffffffffu, sum1, 1);
            sum1 += __shfl_xor_sync(0xffffffffu, sum1, 2);

            m_[mt][0] = mx0; m_[mt][1] = mx1;
            l_[mt][0] = l_[mt][0] * al0 + sum0;
            l_[mt][1] = l_[mt][1] * al1 + sum1;
#pragma unroll
            for (int nt = 0; nt < 8; nt++) {
                oacc[mt][nt][0] *= al0; oacc[mt][nt][1] *= al0;
                oacc[mt][nt][2] *= al1; oacc[mt][nt][3] *= al1;
            }
        }
        __syncwarp();   // Ps rows are warp-private

        // ---- O += P V ----
#pragma unroll
        for (int ks = 0; ks < 4; ks++) {
            int k16 = ks * 16;
            unsigned ua[2][4], ubs[8][2];
#pragma unroll
            for (int mt = 0; mt < 2; mt++)
                ldsm4(ua[mt][0], ua[mt][1], ua[mt][2], ua[mt][3],
                      &Ps[(wm + mt * 16 + la_row) * SQ + k16 + la_col]);
#pragma unroll
            for (int nt2 = 0; nt2 < 4; nt2++) {
                unsigned r0, r1, r2, r3;
                ldsm4(r0, r1, r2, r3,
                      &Vs[(nt2 * 16 + lb_row) * SQ + k16 + lb_col]);
                ubs[nt2 * 2][0] = r0;  ubs[nt2 * 2][1] = r1;
                ubs[nt2 * 2 + 1][0] = r2;  ubs[nt2 * 2 + 1][1] = r3;
            }
#pragma unroll
            for (int mt = 0; mt < 2; mt++)
#pragma unroll
                for (int nt = 0; nt < 8; nt++)
                    mma_bf16(oacc[mt][nt], ua[mt], ubs[nt]);
        }
    }

    // final normalize + write [B,S,H*64] fp32
#pragma unroll
    for (int mt = 0; mt < 2; mt++) {
        float l0 = 1.f / l_[mt][0];
        float l1 = 1.f / l_[mt][1];
        int rowg = qbase + wm + mt * 16 + r;
#pragma unroll
        for (int nt = 0; nt < 8; nt++) {
            int cc = h * 64 + nt * 8 + 2 * c;
            *(float2*)&O[(size_t)(b * 2048 + rowg) * 1024 + cc] =
                make_float2(oacc[mt][nt][0] * l0, oacc[mt][nt][1] * l0);
            *(float2*)&O[(size_t)(b * 2048 + rowg + 8) * 1024 + cc] =
                make_float2(oacc[mt][nt][2] * l1, oacc[mt][nt][3] * l1);
        }
    }
}

// ---------------------------------------------------------------------------
// residual + LayerNorm
// ---------------------------------------------------------------------------
__global__ void __launch_bounds__(256) ln_kernel(
    const float* __restrict__ Y, const float* __restrict__ R,
    const float* __restrict__ g, const float* __restrict__ bt,
    float* __restrict__ out)
{
    __shared__ float red[2][8];
    int row = blockIdx.x;
    int tid = threadIdx.x;
    int lane = tid & 31, wid = tid >> 5;

    float4 y4 = ((const float4*)(Y + (size_t)row * 1024))[tid];
    float4 r4 = ((const float4*)(R + (size_t)row * 1024))[tid];
    float x0 = y4.x + r4.x, x1 = y4.y + r4.y, x2 = y4.z + r4.z, x3 = y4.w + r4.w;

    float sum = x0 + x1 + x2 + x3;
    float sq  = x0 * x0 + x1 * x1 + x2 * x2 + x3 * x3;
#pragma unroll
    for (int off = 16; off > 0; off >>= 1) {
        sum += __shfl_xor_sync(0xffffffff, sum, off);
        sq  += __shfl_xor_sync(0xffffffff, sq,  off);
    }
    if (lane == 0) { red[0][wid] = sum; red[1][wid] = sq; }
    __syncthreads();
    if (tid == 0) {
        float ts = 0.f, tq = 0.f;
#pragma unroll
        for (int w = 0; w < 8; w++) { ts += red[0][w]; tq += red[1][w]; }
        red[0][0] = ts; red[1][0] = tq;
    }
    __syncthreads();
    float mu  = red[0][0] * (1.f / 1024.f);
    float var = red[1][0] * (1.f / 1024.f) - mu * mu;
    float rstd = rsqrtf(var + 1e-6f);

    float4 g4 = ((const float4*)g)[tid];
    float4 b4 = ((const float4*)bt)[tid];
    float4 o;
    o.x = (x0 - mu) * rstd * g4.x + b4.x;
    o.y = (x1 - mu) * rstd * g4.y + b4.y;
    o.z = (x2 - mu) * rstd * g4.z + b4.z;
    o.w = (x3 - mu) * rstd * g4.w + b4.w;
    ((float4*)(out + (size_t)row * 1024))[tid] = o;
}

// ---------------------------------------------------------------------------
extern "C" void kernel_launch(void* const* d_in, const int* in_sizes, int n_in,
                              void* d_out, int out_size)
{
    const float* query = (const float*)d_in[0];
    const float* key   = (const float*)d_in[1];
    const float* value = (const float*)d_in[2];
    const int*   mask  = (const int*)d_in[3];
    const float* w_qs  = (const float*)d_in[4];
    const float* w_ks  = (const float*)d_in[5];
    const float* w_vs  = (const float*)d_in[6];
    const float* w_out = (const float*)d_in[7];
    const float* ln_g  = (const float*)d_in[8];
    const float* ln_b  = (const float*)d_in[9];
    float* out = (float*)d_out;

    __nv_bfloat16 *q, *k, *v;
    float *attn, *y;
    cudaGetSymbolAddress((void**)&q,    g_q);
    cudaGetSymbolAddress((void**)&k,    g_k);
    cudaGetSymbolAddress((void**)&v,    g_v);
    cudaGetSymbolAddress((void**)&attn, g_attn);
    cudaGetSymbolAddress((void**)&y,    g_y);

    cudaFuncSetAttribute(attn_tc,
                         cudaFuncAttributeMaxDynamicSharedMemorySize,
                         ATTN_SMEM);

    dim3 gg(8, 64);   // N/128, M/128 for M=8192, N=1024

    gemm_tc<<<gg, 256>>>(query, w_qs, q, 8192, 1024, 1024, 1);
    gemm_tc<<<gg, 256>>>(key,   w_ks, k, 8192, 1024, 1024, 1);
    gemm_tc<<<gg, 256>>>(value, w_vs, v, 8192, 1024, 1024, 2);

    attn_tc<<<dim3(16, 16, 4), 128, ATTN_SMEM>>>(q, k, v, mask, attn);

    gemm_tc<<<gg, 256>>>(attn, w_out, y, 8192, 1024, 1024, 0);

    ln_kernel<<<8192, 256>>>(y, query, ln_g, ln_b, out);
}